// round 5
// baseline (speedup 1.0000x reference)
#include <cuda_runtime.h>
#include <math.h>

#define BB 64
#define TT 256
#define FF 64
#define UU 512
#define G4U 2048
#define NROW (BB*TT)      // 16384
#define NCTA_REC 128

// ---------------- scratch (device globals: allocation-free rule) ----------------
__device__ float g_Xg[NROW * G4U];        // x@Wx+b per layer (134 MB, reused)
__device__ float g_H0[NROW * UU];         // h sequence, [b*T+t][U] layout
__device__ float g_H1[NROW * UU];
__device__ float g_Ht[TT * UU * BB];      // h sequence, step-major [t][u][b]
__device__ float g_zeros[BB * UU];        // never written -> zero-init
__device__ float g_cF[2 * BB * UU];
__device__ float g_hF[2 * BB * UU];
__device__ float g_cDump[BB * UU];
__device__ float g_hDump[BB * UU];
__device__ unsigned g_barCount = 0;
__device__ unsigned g_barGen = 0;

// ---------------- packed f32x2 helpers (Blackwell; ptxas never emits these) ----------------
typedef unsigned long long u64;

__device__ __forceinline__ u64 pack2(float lo, float hi) {
    u64 r; asm("mov.b64 %0, {%1, %2};" : "=l"(r) : "f"(lo), "f"(hi)); return r;
}
__device__ __forceinline__ u64 splat2(float v) {
    u64 r; asm("mov.b64 %0, {%1, %1};" : "=l"(r) : "f"(v)); return r;
}
__device__ __forceinline__ void unpack2(u64 p, float& lo, float& hi) {
    asm("mov.b64 {%0, %1}, %2;" : "=f"(lo), "=f"(hi) : "l"(p));
}
__device__ __forceinline__ u64 ffma2(u64 a, u64 b, u64 c) {
    u64 d; asm("fma.rn.f32x2 %0, %1, %2, %3;" : "=l"(d) : "l"(a), "l"(b), "l"(c)); return d;
}
__device__ __forceinline__ u64 fadd2(u64 a, u64 b) {
    u64 d; asm("add.rn.f32x2 %0, %1, %2;" : "=l"(d) : "l"(a), "l"(b)); return d;
}

// ---------------- grid-wide barrier (all 128 CTAs co-resident, 1 CTA/SM) ----------------
__device__ __forceinline__ void grid_sync_all() {
    __syncthreads();
    if (threadIdx.x == 0) {
        __threadfence();
        unsigned gen = *(volatile unsigned*)&g_barGen;
        unsigned arr = atomicAdd(&g_barCount, 1u);
        if (arr == gridDim.x - 1) {
            g_barCount = 0;
            __threadfence();
            atomicAdd(&g_barGen, 1u);
        } else {
            while (*(volatile unsigned*)&g_barGen == gen) { }
        }
        __threadfence();
    }
    __syncthreads();
}

__device__ __forceinline__ float sigf(float x) { return 1.0f / (1.0f + expf(-x)); }

// ---------------- parallel GEMM: C[M,N] = A[M,K] @ W[K,N] + bias (f32x2 core) ----------------
__global__ __launch_bounds__(256) void xgemm_kernel(
    const float* __restrict__ A, const float* __restrict__ W,
    const float* __restrict__ bias, float* __restrict__ C,
    int M, int N, int K)
{
    __shared__ float As[16][68];        // As[k][m]
    __shared__ float Bs2[16][136];      // splatted pairs: Bs2[k][2n..2n+1] = (b_n, b_n)
    const int tid = threadIdx.x;
    const int bm = blockIdx.y * 64;
    const int bn = blockIdx.x * 64;
    const int tx = tid & 15;       // n quad
    const int ty = tid >> 4;       // m quad
    const int lr  = tid >> 2;      // A load row
    const int lkq = tid & 3;       // A load k-quad
    const int lk  = tid >> 4;      // W load k
    const int lnq = tid & 15;      // W load n-quad

    u64 acc01[4], acc23[4];
#pragma unroll
    for (int j = 0; j < 4; j++) { acc01[j] = 0ull; acc23[j] = 0ull; }

    for (int k0 = 0; k0 < K; k0 += 16) {
        float4 av = *(const float4*)(A + (size_t)(bm + lr) * K + k0 + lkq * 4);
        float4 wv = *(const float4*)(W + (size_t)(k0 + lk) * N + bn + lnq * 4);
        __syncthreads();
        As[lkq*4+0][lr] = av.x; As[lkq*4+1][lr] = av.y;
        As[lkq*4+2][lr] = av.z; As[lkq*4+3][lr] = av.w;
        {
            ulonglong2 s01; s01.x = splat2(wv.x); s01.y = splat2(wv.y);
            ulonglong2 s23; s23.x = splat2(wv.z); s23.y = splat2(wv.w);
            *(ulonglong2*)&Bs2[lk][lnq*8]     = s01;
            *(ulonglong2*)&Bs2[lk][lnq*8 + 4] = s23;
        }
        __syncthreads();
#pragma unroll
        for (int kk = 0; kk < 16; ++kk) {
            ulonglong2 a  = *(const ulonglong2*)&As[kk][ty*4];
            ulonglong2 b0 = *(const ulonglong2*)&Bs2[kk][tx*8];
            ulonglong2 b1 = *(const ulonglong2*)&Bs2[kk][tx*8+4];
            acc01[0] = ffma2(a.x, b0.x, acc01[0]);
            acc01[1] = ffma2(a.x, b0.y, acc01[1]);
            acc01[2] = ffma2(a.x, b1.x, acc01[2]);
            acc01[3] = ffma2(a.x, b1.y, acc01[3]);
            acc23[0] = ffma2(a.y, b0.x, acc23[0]);
            acc23[1] = ffma2(a.y, b0.y, acc23[1]);
            acc23[2] = ffma2(a.y, b1.x, acc23[2]);
            acc23[3] = ffma2(a.y, b1.y, acc23[3]);
        }
    }
    float4 bv = *(const float4*)(bias + bn + tx * 4);
    float r0v[4], r1v[4], r2v[4], r3v[4];
#pragma unroll
    for (int j = 0; j < 4; j++) {
        unpack2(acc01[j], r0v[j], r1v[j]);
        unpack2(acc23[j], r2v[j], r3v[j]);
    }
    float4 o0 = make_float4(r0v[0]+bv.x, r0v[1]+bv.y, r0v[2]+bv.z, r0v[3]+bv.w);
    float4 o1 = make_float4(r1v[0]+bv.x, r1v[1]+bv.y, r1v[2]+bv.z, r1v[3]+bv.w);
    float4 o2 = make_float4(r2v[0]+bv.x, r2v[1]+bv.y, r2v[2]+bv.z, r2v[3]+bv.w);
    float4 o3 = make_float4(r3v[0]+bv.x, r3v[1]+bv.y, r3v[2]+bv.z, r3v[3]+bv.w);
    *(float4*)(C + (size_t)(bm + ty*4 + 0) * N + bn + tx * 4) = o0;
    *(float4*)(C + (size_t)(bm + ty*4 + 1) * N + bn + tx * 4) = o1;
    *(float4*)(C + (size_t)(bm + ty*4 + 2) * N + bn + tx * 4) = o2;
    *(float4*)(C + (size_t)(bm + ty*4 + 3) * N + bn + tx * 4) = o3;
}

// ---------------- persistent LSTM recurrence ----------------
// 1024 threads, 4-way k-split, f32x2 math, pre-splatted smem weights.
// gates(t) = Xg[b*T+t,:] + h(t-1) @ Wh, gate order (i,j,f,o) in 512-col blocks.
// CTA owns u-range [cta*4, cta*4+4) for all 4 gates & all 64 batch rows.
// smem: hT[512][68] f32 | ws2[512][16] u64 (splatted) | gb[16][72] f32 | pb[3*256] u64x2
#define SM_HT   (512*68)                 // floats
#define SM_WS2  (512*16)                 // u64 count (= 2 floats each)
#define SM_GB   (16*72)                  // floats
#define SM_PB   (3*256*4)                // floats (3 partials x 256 thr x 16B)
#define REC_SMEM ((SM_HT + 2*SM_WS2 + SM_GB + SM_PB) * 4)   // 221,696 B

__global__ __launch_bounds__(1024) void lstm_recur_kernel(
    const float* __restrict__ Xg, const float* __restrict__ Wh,
    const float* __restrict__ c_init, const float* __restrict__ h_init,
    float* __restrict__ Ht,                      // [t][u][b] step-major
    float* __restrict__ Hbt,                     // [b*T+t][U]
    float* __restrict__ c_fin, float* __restrict__ h_fin)
{
    extern __shared__ float sm[];
    float* hT  = sm;                              // [512][68]
    u64*   ws2 = (u64*)(sm + SM_HT);              // [512][16] splatted weights
    float* gb  = sm + SM_HT + 2 * SM_WS2;         // [16][72]
    float* pb  = gb + SM_GB;                      // [3][256][4]

    const int tid = threadIdx.x;
    const int u0  = blockIdx.x * 4;
    const int colIdx = tid & 15;
    const int rowq = (tid >> 4) & 15;
    const int r0 = rowq * 4;
    const int ks = tid >> 8;                                   // 0..3 k-split quarter
    const int col = ((colIdx >> 2) << 9) + u0 + (colIdx & 3);  // gate*512 + u
    // cell-update mapping (tid < 256 only)
    const int ub  = tid & 63;
    const int uuu = (tid >> 6) & 3;
    const int myu = u0 + uuu;
    float creg = (tid < 256) ? c_init[ub * UU + myu] : 0.0f;

    // stage pre-splatted Wh slice (512 x 16 u64) into smem once
    for (int idx = tid; idx < 512 * 16; idx += 1024) {
        int k = idx >> 4, ci = idx & 15;
        int wc = ((ci >> 2) << 9) + u0 + (ci & 3);
        ws2[k * 16 + ci] = splat2(Wh[(size_t)k * G4U + wc]);
    }

    const u64* wp2 = ws2 + ks * 128 * 16 + colIdx;
    const float* hpb = hT + ks * 128 * 68 + r0;

    for (int t = 0; t < TT; ++t) {
        // ---- stage h(t-1) into smem transposed hT[u][b] ----
        if (t == 0) {
            for (int idx = tid; idx < BB * UU; idx += 1024) {
                int u = idx >> 6, b = idx & 63;
                hT[u * 68 + b] = h_init[b * UU + u];
            }
        } else {
            const float4* hp = (const float4*)(Ht + (size_t)(t - 1) * (UU * BB));
            for (int idx4 = tid; idx4 < (BB * UU) / 4; idx4 += 1024) {
                int u = idx4 >> 4, b4 = idx4 & 15;
                *(float4*)(hT + u * 68 + b4 * 4) = hp[idx4];
            }
        }
        __syncthreads();

        // Xg terms: issued now, consumed AFTER the k-loop (latency hidden)
        float xa0 = 0.f, xa1 = 0.f, xa2 = 0.f, xa3 = 0.f;
        if (ks == 0) {
            const float* xgp = Xg + (size_t)t * G4U + col;
            xa0 = xgp[(size_t)(r0 + 0) * TT * G4U];
            xa1 = xgp[(size_t)(r0 + 1) * TT * G4U];
            xa2 = xgp[(size_t)(r0 + 2) * TT * G4U];
            xa3 = xgp[(size_t)(r0 + 3) * TT * G4U];
        }

        // ---- partial GEMM over this thread's 128 k's: 4 instr / 4 MACs ----
        u64 p01 = 0ull, p23 = 0ull;
#pragma unroll 8
        for (int kk = 0; kk < 128; ++kk) {
            u64 w2 = wp2[kk * 16];                                // LDS.64
            ulonglong2 hv = *(const ulonglong2*)(hpb + kk * 68);  // LDS.128
            p01 = ffma2(hv.x, w2, p01);
            p23 = ffma2(hv.y, w2, p23);
        }

        if (ks) {
            ulonglong2 pv; pv.x = p01; pv.y = p23;
            *(ulonglong2*)(pb + ((ks - 1) * 256 + (tid & 255)) * 4) = pv;
        }
        __syncthreads();
        if (ks == 0) {
            ulonglong2 q0 = *(const ulonglong2*)(pb + (0 * 256 + tid) * 4);
            ulonglong2 q1 = *(const ulonglong2*)(pb + (1 * 256 + tid) * 4);
            ulonglong2 q2 = *(const ulonglong2*)(pb + (2 * 256 + tid) * 4);
            p01 = fadd2(fadd2(p01, q0.x), fadd2(q1.x, q2.x));
            p23 = fadd2(fadd2(p23, q0.y), fadd2(q1.y, q2.y));
            p01 = fadd2(p01, pack2(xa0, xa1));
            p23 = fadd2(p23, pack2(xa2, xa3));
            float g0, g1, g2, g3;
            unpack2(p01, g0, g1);
            unpack2(p23, g2, g3);
            *(float4*)(gb + colIdx * 72 + r0) = make_float4(g0, g1, g2, g3);
        }
        __syncthreads();

        // ---- cell update (CTA-local) ----
        if (tid < 256) {
            float gi = gb[(0  + uuu) * 72 + ub];
            float gj = gb[(4  + uuu) * 72 + ub];
            float gf = gb[(8  + uuu) * 72 + ub];
            float go = gb[(12 + uuu) * 72 + ub];
            float cn = sigf(gf + 1.0f) * creg + sigf(gi) * tanhf(gj);
            float hn = sigf(go) * tanhf(cn);
            creg = cn;
            Ht[(size_t)t * (UU * BB) + myu * BB + ub] = hn;   // coalesced hot path
            Hbt[(size_t)(ub * TT + t) * UU + myu] = hn;       // cold path for next GEMM
            if (t == TT - 1) {
                c_fin[ub * UU + myu] = cn;
                h_fin[ub * UU + myu] = hn;
            }
        }
        grid_sync_all();   // publish h(t)
    }
}

// ---------------- output projection + length mask ----------------
__global__ __launch_bounds__(256) void proj_kernel(
    const float* __restrict__ H, const float* __restrict__ Wo,
    const float* __restrict__ bo, const int* __restrict__ lens,
    float* __restrict__ out)
{
    __shared__ float hs[4][512];
    const int tid = threadIdx.x;
    const int row0 = blockIdx.x * 4;
    for (int idx = tid; idx < 4 * UU; idx += 256)
        hs[idx >> 9][idx & 511] = H[(size_t)row0 * UU + idx];
    __syncthreads();
    const int r = tid >> 6;
    const int c = tid & 63;
    float acc = bo[c];
#pragma unroll 8
    for (int k = 0; k < UU; ++k)
        acc = fmaf(hs[r][k], Wo[k * FF + c], acc);
    const int row = row0 + r;
    const int b = row >> 8;
    const int t = row & 255;
    out[(size_t)row * FF + c] = (t < lens[b]) ? acc : 0.0f;
}

// ---------------- launch ----------------
extern "C" void kernel_launch(void* const* d_in, const int* in_sizes, int n_in,
                              void* d_out, int out_size)
{
    const float* inputs  = (const float*)d_in[0];
    const float* targets = (const float*)d_in[1];
    const int*   tlen    = (const int*)d_in[2];
    const float* eW0 = (const float*)d_in[3];
    const float* eb0 = (const float*)d_in[4];
    const float* eW1 = (const float*)d_in[5];
    const float* eb1 = (const float*)d_in[6];
    const float* dW0 = (const float*)d_in[7];
    const float* db0 = (const float*)d_in[8];
    const float* dW1 = (const float*)d_in[9];
    const float* db1 = (const float*)d_in[10];
    const float* oW  = (const float*)d_in[11];
    const float* ob  = (const float*)d_in[12];
    float* out = (float*)d_out;

    float *Xg, *H0, *H1, *Ht, *zer, *cF, *hF, *cD, *hD;
    cudaGetSymbolAddress((void**)&Xg,  g_Xg);
    cudaGetSymbolAddress((void**)&H0,  g_H0);
    cudaGetSymbolAddress((void**)&H1,  g_H1);
    cudaGetSymbolAddress((void**)&Ht,  g_Ht);
    cudaGetSymbolAddress((void**)&zer, g_zeros);
    cudaGetSymbolAddress((void**)&cF,  g_cF);
    cudaGetSymbolAddress((void**)&hF,  g_hF);
    cudaGetSymbolAddress((void**)&cD,  g_cDump);
    cudaGetSymbolAddress((void**)&hD,  g_hDump);

    cudaFuncSetAttribute(lstm_recur_kernel,
                         cudaFuncAttributeMaxDynamicSharedMemorySize, REC_SMEM);

    dim3 gx(G4U / 64, NROW / 64);   // (32, 256)

    // encoder layer 0
    xgemm_kernel<<<gx, 256>>>(inputs, eW0, eb0, Xg, NROW, G4U, FF);
    lstm_recur_kernel<<<NCTA_REC, 1024, REC_SMEM>>>(Xg, eW0 + (size_t)FF * G4U,
                                                    zer, zer, Ht, H0, cF, hF);
    // encoder layer 1
    xgemm_kernel<<<gx, 256>>>(H0, eW1, eb1, Xg, NROW, G4U, UU);
    lstm_recur_kernel<<<NCTA_REC, 1024, REC_SMEM>>>(Xg, eW1 + (size_t)UU * G4U,
                                                    zer, zer, Ht, H1,
                                                    cF + BB * UU, hF + BB * UU);
    // decoder layer 0 (init = encoder layer-0 finals)
    xgemm_kernel<<<gx, 256>>>(targets, dW0, db0, Xg, NROW, G4U, FF);
    lstm_recur_kernel<<<NCTA_REC, 1024, REC_SMEM>>>(Xg, dW0 + (size_t)FF * G4U,
                                                    cF, hF, Ht, H0, cD, hD);
    // decoder layer 1 (init = encoder layer-1 finals)
    xgemm_kernel<<<gx, 256>>>(H0, dW1, db1, Xg, NROW, G4U, UU);
    lstm_recur_kernel<<<NCTA_REC, 1024, REC_SMEM>>>(Xg, dW1 + (size_t)UU * G4U,
                                                    cF + BB * UU, hF + BB * UU,
                                                    Ht, H1, cD, hD);
    // projection + mask
    proj_kernel<<<NROW / 4, 256>>>(H1, oW, ob, tlen, out);
}

// round 6
// speedup vs baseline: 1.2935x; 1.2935x over previous
#include <cuda_runtime.h>
#include <math.h>

#define BB 64
#define TT 256
#define FF 64
#define UU 512
#define G4U 2048
#define NROW (BB*TT)      // 16384
#define NCTA_REC 128

// ---------------- scratch (device globals: allocation-free rule) ----------------
__device__ float g_Xg[NROW * G4U];
__device__ float g_H0[NROW * UU];
__device__ float g_H1[NROW * UU];
__device__ float g_Ht[TT * UU * BB];      // step-major [t][u][b]
__device__ float g_zeros[BB * UU];
__device__ float g_cF[2 * BB * UU];
__device__ float g_hF[2 * BB * UU];
__device__ float g_cDump[BB * UU];
__device__ float g_hDump[BB * UU];
__device__ unsigned g_barCount = 0;
__device__ unsigned g_barGen = 0;

// ---------------- packed f32x2 helpers ----------------
typedef unsigned long long u64;

__device__ __forceinline__ u64 pack2(float lo, float hi) {
    u64 r; asm("mov.b64 %0, {%1, %2};" : "=l"(r) : "f"(lo), "f"(hi)); return r;
}
__device__ __forceinline__ u64 splat2(float v) {
    u64 r; asm("mov.b64 %0, {%1, %1};" : "=l"(r) : "f"(v)); return r;
}
__device__ __forceinline__ void unpack2(u64 p, float& lo, float& hi) {
    asm("mov.b64 {%0, %1}, %2;" : "=f"(lo), "=f"(hi) : "l"(p));
}
__device__ __forceinline__ u64 ffma2(u64 a, u64 b, u64 c) {
    u64 d; asm("fma.rn.f32x2 %0, %1, %2, %3;" : "=l"(d) : "l"(a), "l"(b), "l"(c)); return d;
}
__device__ __forceinline__ u64 fadd2(u64 a, u64 b) {
    u64 d; asm("add.rn.f32x2 %0, %1, %2;" : "=l"(d) : "l"(a), "l"(b)); return d;
}

// ---------------- grid-wide barrier ----------------
__device__ __forceinline__ void grid_sync_all() {
    __syncthreads();
    if (threadIdx.x == 0) {
        __threadfence();
        unsigned gen = *(volatile unsigned*)&g_barGen;
        unsigned arr = atomicAdd(&g_barCount, 1u);
        if (arr == gridDim.x - 1) {
            g_barCount = 0;
            __threadfence();
            atomicAdd(&g_barGen, 1u);
        } else {
            while (*(volatile unsigned*)&g_barGen == gen) { }
        }
        __threadfence();
    }
    __syncthreads();
}

// fast activations (MUFU-based; rel err ~1e-6, tolerance is 1e-3)
__device__ __forceinline__ float fsig(float x) {
    return __fdividef(1.0f, 1.0f + __expf(-x));
}
__device__ __forceinline__ float ftanh(float x) {
    float t = __expf(2.0f * x);                  // -> inf / 0 at extremes: still correct
    return 1.0f - 2.0f * __fdividef(1.0f, t + 1.0f);
}

// ---------------- parallel GEMM: C[M,N] = A[M,K] @ W[K,N] + bias (f32x2 core) ----------------
__global__ __launch_bounds__(256) void xgemm_kernel(
    const float* __restrict__ A, const float* __restrict__ W,
    const float* __restrict__ bias, float* __restrict__ C,
    int M, int N, int K)
{
    __shared__ float As[16][68];
    __shared__ float Bs2[16][136];
    const int tid = threadIdx.x;
    const int bm = blockIdx.y * 64;
    const int bn = blockIdx.x * 64;
    const int tx = tid & 15;
    const int ty = tid >> 4;
    const int lr  = tid >> 2;
    const int lkq = tid & 3;
    const int lk  = tid >> 4;
    const int lnq = tid & 15;

    u64 acc01[4], acc23[4];
#pragma unroll
    for (int j = 0; j < 4; j++) { acc01[j] = 0ull; acc23[j] = 0ull; }

    for (int k0 = 0; k0 < K; k0 += 16) {
        float4 av = *(const float4*)(A + (size_t)(bm + lr) * K + k0 + lkq * 4);
        float4 wv = *(const float4*)(W + (size_t)(k0 + lk) * N + bn + lnq * 4);
        __syncthreads();
        As[lkq*4+0][lr] = av.x; As[lkq*4+1][lr] = av.y;
        As[lkq*4+2][lr] = av.z; As[lkq*4+3][lr] = av.w;
        {
            ulonglong2 s01; s01.x = splat2(wv.x); s01.y = splat2(wv.y);
            ulonglong2 s23; s23.x = splat2(wv.z); s23.y = splat2(wv.w);
            *(ulonglong2*)&Bs2[lk][lnq*8]     = s01;
            *(ulonglong2*)&Bs2[lk][lnq*8 + 4] = s23;
        }
        __syncthreads();
#pragma unroll
        for (int kk = 0; kk < 16; ++kk) {
            ulonglong2 a  = *(const ulonglong2*)&As[kk][ty*4];
            ulonglong2 b0 = *(const ulonglong2*)&Bs2[kk][tx*8];
            ulonglong2 b1 = *(const ulonglong2*)&Bs2[kk][tx*8+4];
            acc01[0] = ffma2(a.x, b0.x, acc01[0]);
            acc01[1] = ffma2(a.x, b0.y, acc01[1]);
            acc01[2] = ffma2(a.x, b1.x, acc01[2]);
            acc01[3] = ffma2(a.x, b1.y, acc01[3]);
            acc23[0] = ffma2(a.y, b0.x, acc23[0]);
            acc23[1] = ffma2(a.y, b0.y, acc23[1]);
            acc23[2] = ffma2(a.y, b1.x, acc23[2]);
            acc23[3] = ffma2(a.y, b1.y, acc23[3]);
        }
    }
    float4 bv = *(const float4*)(bias + bn + tx * 4);
    float r0v[4], r1v[4], r2v[4], r3v[4];
#pragma unroll
    for (int j = 0; j < 4; j++) {
        unpack2(acc01[j], r0v[j], r1v[j]);
        unpack2(acc23[j], r2v[j], r3v[j]);
    }
    float4 o0 = make_float4(r0v[0]+bv.x, r0v[1]+bv.y, r0v[2]+bv.z, r0v[3]+bv.w);
    float4 o1 = make_float4(r1v[0]+bv.x, r1v[1]+bv.y, r1v[2]+bv.z, r1v[3]+bv.w);
    float4 o2 = make_float4(r2v[0]+bv.x, r2v[1]+bv.y, r2v[2]+bv.z, r2v[3]+bv.w);
    float4 o3 = make_float4(r3v[0]+bv.x, r3v[1]+bv.y, r3v[2]+bv.z, r3v[3]+bv.w);
    *(float4*)(C + (size_t)(bm + ty*4 + 0) * N + bn + tx * 4) = o0;
    *(float4*)(C + (size_t)(bm + ty*4 + 1) * N + bn + tx * 4) = o1;
    *(float4*)(C + (size_t)(bm + ty*4 + 2) * N + bn + tx * 4) = o2;
    *(float4*)(C + (size_t)(bm + ty*4 + 3) * N + bn + tx * 4) = o3;
}

// ---------------- persistent LSTM recurrence ----------------
// 512 threads. Thread microtile: 8 batch rows x 2 gate-cols, 8-way k-split (64 k each).
//   colg = tid&7 (cols 2*colg, 2*colg+1 of 16), rowg = (tid>>3)&7 (rows 8*rowg), ks = tid>>6.
// Inner iter: LDS.64 w + 2 splat + 2 LDS.128 h + 8 FFMA2  -> 3 LDS wf / 8 FFMA2.
// smem: hT[512][68] f32 | ws[512][16] f32 raw | gb[16][72] f32 | pb[4][7][64] ull2
#define SM_HT  (512*68)
#define SM_WS  (512*16)
#define SM_GB  (16*72)
#define SM_PB4 (4*7*64*4)                 // floats (ull2 = 4 floats)
#define REC_SMEM ((SM_HT + SM_WS + SM_GB + SM_PB4) * 4)   // 205,312 B

__global__ __launch_bounds__(512) void lstm_recur_kernel(
    const float* __restrict__ Xg, const float* __restrict__ Wh,
    const float* __restrict__ c_init, const float* __restrict__ h_init,
    float* __restrict__ Ht, float* __restrict__ Hbt,
    float* __restrict__ c_fin, float* __restrict__ h_fin)
{
    extern __shared__ float sm[];
    float*      hT = sm;                          // [512][68]
    float*      ws = sm + SM_HT;                  // [512][16] raw weights
    float*      gb = ws + SM_WS;                  // [16][72] recurrent gate parts
    ulonglong2* pb = (ulonglong2*)(gb + SM_GB);   // [4][7][64]

    const int tid  = threadIdx.x;
    const int u0   = blockIdx.x * 4;
    const int colg = tid & 7;
    const int rowg = (tid >> 3) & 7;
    const int ks   = tid >> 6;            // 0..7
    const int slot = tid & 63;            // (rowg,colg)
    // update-thread mapping (tid < 256)
    const int ub  = tid & 63;
    const int uuu = tid >> 6;             // valid when tid<256
    const int myu = u0 + (uuu & 3);
    float creg = (tid < 256) ? c_init[ub * UU + myu] : 0.0f;

    // stage raw Wh slice [512 x 16] once
    for (int idx = tid; idx < 512 * 16; idx += 512) {
        int k = idx >> 4, c = idx & 15;
        int wc = ((c >> 2) << 9) + u0 + (c & 3);
        ws[k * 16 + c] = Wh[(size_t)k * G4U + wc];
    }

    const float2* wp = (const float2*)ws + ks * 64 * 8 + colg;
    const float*  hp = hT + ks * 64 * 68 + rowg * 8;

    for (int t = 0; t < TT; ++t) {
        // Xg preload (update threads): 4 scattered LDG, consumed after 2 syncs
        float xgi = 0.f, xgj = 0.f, xgf = 0.f, xgo = 0.f;
        if (tid < 256) {
            const float* xp = Xg + (size_t)(ub * TT + t) * G4U + myu;
            xgi = xp[0];   xgj = xp[512];
            xgf = xp[1024]; xgo = xp[1536];
        }

        // ---- stage h(t-1) into hT[u][b] ----
        if (t == 0) {
            for (int idx = tid; idx < BB * UU; idx += 512) {
                int u = idx >> 6, b = idx & 63;
                hT[u * 68 + b] = h_init[b * UU + u];
            }
        } else {
            const float4* hsrc = (const float4*)(Ht + (size_t)(t - 1) * (UU * BB));
            for (int idx4 = tid; idx4 < (BB * UU) / 4; idx4 += 512) {
                int u = idx4 >> 4, b4 = idx4 & 15;
                *(float4*)(hT + u * 68 + b4 * 4) = hsrc[idx4];
            }
        }
        __syncthreads();

        // ---- microtile GEMM: 8 rows x 2 cols over 64 k ----
        u64 a0[4], a1[4];
#pragma unroll
        for (int i = 0; i < 4; i++) { a0[i] = 0ull; a1[i] = 0ull; }
#pragma unroll 8
        for (int kk = 0; kk < 64; ++kk) {
            float2 w = wp[kk * 8];
            u64 w0 = splat2(w.x);
            u64 w1 = splat2(w.y);
            ulonglong2 ha = *(const ulonglong2*)(hp + kk * 68);       // rows 0-3
            ulonglong2 hb = *(const ulonglong2*)(hp + kk * 68 + 4);   // rows 4-7
            a0[0] = ffma2(ha.x, w0, a0[0]);
            a0[1] = ffma2(ha.y, w0, a0[1]);
            a0[2] = ffma2(hb.x, w0, a0[2]);
            a0[3] = ffma2(hb.y, w0, a0[3]);
            a1[0] = ffma2(ha.x, w1, a1[0]);
            a1[1] = ffma2(ha.y, w1, a1[1]);
            a1[2] = ffma2(hb.x, w1, a1[2]);
            a1[3] = ffma2(hb.y, w1, a1[3]);
        }

        // ---- k-split reduction ----
        if (ks) {
#pragma unroll
            for (int i = 0; i < 4; i++) {
                ulonglong2 v; v.x = a0[i]; v.y = a1[i];
                pb[(i * 7 + (ks - 1)) * 64 + slot] = v;   // conflict-free STS.128
            }
        }
        __syncthreads();
        if (ks == 0) {
#pragma unroll
            for (int i = 0; i < 4; i++) {
#pragma unroll
                for (int j = 0; j < 7; j++) {
                    ulonglong2 q = pb[(i * 7 + j) * 64 + slot];
                    a0[i] = fadd2(a0[i], q.x);
                    a1[i] = fadd2(a1[i], q.y);
                }
            }
            // write recurrent gate parts: gb[col][row], rows packed in pairs
            float* g0 = gb + (2 * colg) * 72 + rowg * 8;
            float* g1 = gb + (2 * colg + 1) * 72 + rowg * 8;
            ulonglong2 v0a; v0a.x = a0[0]; v0a.y = a0[1];
            ulonglong2 v0b; v0b.x = a0[2]; v0b.y = a0[3];
            ulonglong2 v1a; v1a.x = a1[0]; v1a.y = a1[1];
            ulonglong2 v1b; v1b.x = a1[2]; v1b.y = a1[3];
            *(ulonglong2*)(g0)     = v0a;
            *(ulonglong2*)(g0 + 4) = v0b;
            *(ulonglong2*)(g1)     = v1a;
            *(ulonglong2*)(g1 + 4) = v1b;
        }
        __syncthreads();

        // ---- cell update (tid < 256) ----
        if (tid < 256) {
            float gi = xgi + gb[(0  + uuu) * 72 + ub];
            float gj = xgj + gb[(4  + uuu) * 72 + ub];
            float gf = xgf + gb[(8  + uuu) * 72 + ub];
            float go = xgo + gb[(12 + uuu) * 72 + ub];
            float cn = fsig(gf + 1.0f) * creg + fsig(gi) * ftanh(gj);
            float hn = fsig(go) * ftanh(cn);
            creg = cn;
            Ht[(size_t)t * (UU * BB) + myu * BB + ub] = hn;
            Hbt[(size_t)(ub * TT + t) * UU + myu] = hn;
            if (t == TT - 1) {
                c_fin[ub * UU + myu] = cn;
                h_fin[ub * UU + myu] = hn;
            }
        }
        grid_sync_all();
    }
}

// ---------------- output projection + length mask ----------------
__global__ __launch_bounds__(256) void proj_kernel(
    const float* __restrict__ H, const float* __restrict__ Wo,
    const float* __restrict__ bo, const int* __restrict__ lens,
    float* __restrict__ out)
{
    __shared__ float hs[4][512];
    const int tid = threadIdx.x;
    const int row0 = blockIdx.x * 4;
    for (int idx = tid; idx < 4 * UU; idx += 256)
        hs[idx >> 9][idx & 511] = H[(size_t)row0 * UU + idx];
    __syncthreads();
    const int r = tid >> 6;
    const int c = tid & 63;
    float acc = bo[c];
#pragma unroll 8
    for (int k = 0; k < UU; ++k)
        acc = fmaf(hs[r][k], Wo[k * FF + c], acc);
    const int row = row0 + r;
    const int b = row >> 8;
    const int t = row & 255;
    out[(size_t)row * FF + c] = (t < lens[b]) ? acc : 0.0f;
}

// ---------------- launch ----------------
extern "C" void kernel_launch(void* const* d_in, const int* in_sizes, int n_in,
                              void* d_out, int out_size)
{
    const float* inputs  = (const float*)d_in[0];
    const float* targets = (const float*)d_in[1];
    const int*   tlen    = (const int*)d_in[2];
    const float* eW0 = (const float*)d_in[3];
    const float* eb0 = (const float*)d_in[4];
    const float* eW1 = (const float*)d_in[5];
    const float* eb1 = (const float*)d_in[6];
    const float* dW0 = (const float*)d_in[7];
    const float* db0 = (const float*)d_in[8];
    const float* dW1 = (const float*)d_in[9];
    const float* db1 = (const float*)d_in[10];
    const float* oW  = (const float*)d_in[11];
    const float* ob  = (const float*)d_in[12];
    float* out = (float*)d_out;

    float *Xg, *H0, *H1, *Ht, *zer, *cF, *hF, *cD, *hD;
    cudaGetSymbolAddress((void**)&Xg,  g_Xg);
    cudaGetSymbolAddress((void**)&H0,  g_H0);
    cudaGetSymbolAddress((void**)&H1,  g_H1);
    cudaGetSymbolAddress((void**)&Ht,  g_Ht);
    cudaGetSymbolAddress((void**)&zer, g_zeros);
    cudaGetSymbolAddress((void**)&cF,  g_cF);
    cudaGetSymbolAddress((void**)&hF,  g_hF);
    cudaGetSymbolAddress((void**)&cD,  g_cDump);
    cudaGetSymbolAddress((void**)&hD,  g_hDump);

    cudaFuncSetAttribute(lstm_recur_kernel,
                         cudaFuncAttributeMaxDynamicSharedMemorySize, REC_SMEM);

    dim3 gx(G4U / 64, NROW / 64);   // (32, 256)

    // encoder layer 0
    xgemm_kernel<<<gx, 256>>>(inputs, eW0, eb0, Xg, NROW, G4U, FF);
    lstm_recur_kernel<<<NCTA_REC, 512, REC_SMEM>>>(Xg, eW0 + (size_t)FF * G4U,
                                                   zer, zer, Ht, H0, cF, hF);
    // encoder layer 1
    xgemm_kernel<<<gx, 256>>>(H0, eW1, eb1, Xg, NROW, G4U, UU);
    lstm_recur_kernel<<<NCTA_REC, 512, REC_SMEM>>>(Xg, eW1 + (size_t)UU * G4U,
                                                   zer, zer, Ht, H1,
                                                   cF + BB * UU, hF + BB * UU);
    // decoder layer 0 (init = encoder layer-0 finals)
    xgemm_kernel<<<gx, 256>>>(targets, dW0, db0, Xg, NROW, G4U, FF);
    lstm_recur_kernel<<<NCTA_REC, 512, REC_SMEM>>>(Xg, dW0 + (size_t)FF * G4U,
                                                   cF, hF, Ht, H0, cD, hD);
    // decoder layer 1 (init = encoder layer-1 finals)
    xgemm_kernel<<<gx, 256>>>(H0, dW1, db1, Xg, NROW, G4U, UU);
    lstm_recur_kernel<<<NCTA_REC, 512, REC_SMEM>>>(Xg, dW1 + (size_t)UU * G4U,
                                                   cF + BB * UU, hF + BB * UU,
                                                   Ht, H1, cD, hD);
    // projection + mask
    proj_kernel<<<NROW / 4, 256>>>(H1, oW, ob, tlen, out);
}

// round 7
// speedup vs baseline: 1.5253x; 1.1792x over previous
#include <cuda_runtime.h>
#include <cuda_bf16.h>
#include <math.h>

#define BB 64
#define TT 256
#define FF 64
#define UU 512
#define G4U 2048
#define NROW (BB*TT)      // 16384
#define NCTA_REC 128

// ---------------- scratch (device globals: allocation-free rule) ----------------
__device__ float g_Xg[NROW * G4U];        // x@Wx+b, TRANSPOSED layout [t][col][b]
__device__ float g_H0[NROW * UU];         // h sequence, [b*T+t][U] (for next xgemm/proj)
__device__ float g_H1[NROW * UU];
__device__ float g_Ht[TT * UU * BB];      // h frag words: [t][p][u/2][b] (bf16 hi/lo pairs)
__device__ float g_zeros[BB * UU];
__device__ float g_cF[2 * BB * UU];
__device__ float g_hF[2 * BB * UU];
__device__ float g_cDump[BB * UU];
__device__ float g_hDump[BB * UU];
__device__ unsigned g_barCount = 0;
__device__ unsigned g_barGen = 0;

typedef unsigned long long u64;
typedef unsigned int u32;

// ---------------- packed f32x2 helpers (for xgemm) ----------------
__device__ __forceinline__ u64 splat2(float v) {
    u64 r; asm("mov.b64 %0, {%1, %1};" : "=l"(r) : "f"(v)); return r;
}
__device__ __forceinline__ void unpack2(u64 p, float& lo, float& hi) {
    asm("mov.b64 {%0, %1}, %2;" : "=f"(lo), "=f"(hi) : "l"(p));
}
__device__ __forceinline__ u64 ffma2(u64 a, u64 b, u64 c) {
    u64 d; asm("fma.rn.f32x2 %0, %1, %2, %3;" : "=l"(d) : "l"(a), "l"(b), "l"(c)); return d;
}

// ---------------- bf16 split helpers ----------------
__device__ __forceinline__ void bf16_split(float v, unsigned short& hi, unsigned short& lo) {
    __nv_bfloat16 h = __float2bfloat16(v);
    __nv_bfloat16 l = __float2bfloat16(v - __bfloat162float(h));
    hi = __bfloat16_as_ushort(h);
    lo = __bfloat16_as_ushort(l);
}
__device__ __forceinline__ u32 pack16(unsigned short a, unsigned short b) {
    return (u32)a | ((u32)b << 16);   // low half = first (even-k) element
}

// ---------------- mma m16n8k16 bf16 ----------------
__device__ __forceinline__ void mma_bf16(float* d, u32 a0, u32 a1, u32 a2, u32 a3,
                                         u32 b0, u32 b1) {
    asm volatile(
        "mma.sync.aligned.m16n8k16.row.col.f32.bf16.bf16.f32 "
        "{%0,%1,%2,%3}, {%4,%5,%6,%7}, {%8,%9}, {%0,%1,%2,%3};"
        : "+f"(d[0]), "+f"(d[1]), "+f"(d[2]), "+f"(d[3])
        : "r"(a0), "r"(a1), "r"(a2), "r"(a3), "r"(b0), "r"(b1));
}

// ---------------- grid-wide barrier (proven) ----------------
__device__ __forceinline__ void grid_sync_all() {
    __syncthreads();
    if (threadIdx.x == 0) {
        __threadfence();
        unsigned gen = *(volatile unsigned*)&g_barGen;
        unsigned arr = atomicAdd(&g_barCount, 1u);
        if (arr == gridDim.x - 1) {
            g_barCount = 0;
            __threadfence();
            atomicAdd(&g_barGen, 1u);
        } else {
            while (*(volatile unsigned*)&g_barGen == gen) { }
        }
        __threadfence();
    }
    __syncthreads();
}

__device__ __forceinline__ float fsig(float x) {
    return __fdividef(1.0f, 1.0f + __expf(-x));
}
__device__ __forceinline__ float ftanh(float x) {
    float t = __expf(2.0f * x);
    return 1.0f - 2.0f * __fdividef(1.0f, t + 1.0f);
}

// ---------------- parallel GEMM (f32x2), epilogue writes TRANSPOSED Xg [t][col][b] ----------------
__global__ __launch_bounds__(256) void xgemm_kernel(
    const float* __restrict__ A, const float* __restrict__ W,
    const float* __restrict__ bias, float* __restrict__ C,
    int M, int N, int K)
{
    __shared__ float As[16][68];
    __shared__ float Bs2[16][136];
    const int tid = threadIdx.x;
    const int bm = blockIdx.y * 64;
    const int bn = blockIdx.x * 64;
    const int tx = tid & 15;
    const int ty = tid >> 4;
    const int lr  = tid >> 2;
    const int lkq = tid & 3;
    const int lk  = tid >> 4;
    const int lnq = tid & 15;

    u64 acc01[4], acc23[4];
#pragma unroll
    for (int j = 0; j < 4; j++) { acc01[j] = 0ull; acc23[j] = 0ull; }

    for (int k0 = 0; k0 < K; k0 += 16) {
        float4 av = *(const float4*)(A + (size_t)(bm + lr) * K + k0 + lkq * 4);
        float4 wv = *(const float4*)(W + (size_t)(k0 + lk) * N + bn + lnq * 4);
        __syncthreads();
        As[lkq*4+0][lr] = av.x; As[lkq*4+1][lr] = av.y;
        As[lkq*4+2][lr] = av.z; As[lkq*4+3][lr] = av.w;
        {
            ulonglong2 s01; s01.x = splat2(wv.x); s01.y = splat2(wv.y);
            ulonglong2 s23; s23.x = splat2(wv.z); s23.y = splat2(wv.w);
            *(ulonglong2*)&Bs2[lk][lnq*8]     = s01;
            *(ulonglong2*)&Bs2[lk][lnq*8 + 4] = s23;
        }
        __syncthreads();
#pragma unroll
        for (int kk = 0; kk < 16; ++kk) {
            ulonglong2 a  = *(const ulonglong2*)&As[kk][ty*4];
            ulonglong2 b0 = *(const ulonglong2*)&Bs2[kk][tx*8];
            ulonglong2 b1 = *(const ulonglong2*)&Bs2[kk][tx*8+4];
            acc01[0] = ffma2(a.x, b0.x, acc01[0]);
            acc01[1] = ffma2(a.x, b0.y, acc01[1]);
            acc01[2] = ffma2(a.x, b1.x, acc01[2]);
            acc01[3] = ffma2(a.x, b1.y, acc01[3]);
            acc23[0] = ffma2(a.y, b0.x, acc23[0]);
            acc23[1] = ffma2(a.y, b0.y, acc23[1]);
            acc23[2] = ffma2(a.y, b1.x, acc23[2]);
            acc23[3] = ffma2(a.y, b1.y, acc23[3]);
        }
    }
    float4 bv = *(const float4*)(bias + bn + tx * 4);
    float rv[4][4];
#pragma unroll
    for (int j = 0; j < 4; j++) {
        unpack2(acc01[j], rv[0][j], rv[1][j]);
        unpack2(acc23[j], rv[2][j], rv[3][j]);
    }
    const float bias4[4] = {bv.x, bv.y, bv.z, bv.w};
#pragma unroll
    for (int i = 0; i < 4; i++) {
        int row = bm + ty * 4 + i;
        int b = row >> 8;          // M rows are b*T + t
        int t = row & 255;
#pragma unroll
        for (int j = 0; j < 4; j++) {
            int col = bn + tx * 4 + j;
            C[((size_t)t * G4U + col) * BB + b] = rv[i][j] + bias4[j];
        }
    }
}

// ---------------- persistent LSTM recurrence (bf16x2 tensor-core) ----------------
// 256 threads = 8 warps. CTA owns u0..u0+3 (16 gate-cols = M dim of mma).
// Warp w handles k16-chunks q in [4w, 4w+4) for all 8 batch n-tiles; 8-way k reduce in smem.
// gates = Xg[t][col][b] + (Wh^T)[16 x 512] @ hT[512 x 64] via bf16x2 3-term mma.
// smem: hbf[2][256][72] u32 (h frags, pad-72 conflict-free) + pb[8][16][68] f32 partials
#define HBF_PLANE (256*72)
#define SM_HBF (2*HBF_PLANE)          // u32 words
#define SM_PB  (8*16*68)              // floats
#define REC_SMEM ((SM_HBF + SM_PB) * 4)   // 182,272 B

__global__ __launch_bounds__(256) void lstm_recur_kernel(
    const float* __restrict__ Xg, const float* __restrict__ Wh,
    const float* __restrict__ c_init, const float* __restrict__ h_init,
    float* __restrict__ Hf,                      // frag words per step [t][2][256][64]
    float* __restrict__ Hbt,                     // [b*T+t][U] fp32
    float* __restrict__ c_fin, float* __restrict__ h_fin)
{
    extern __shared__ float smraw[];
    u32*   hbf = (u32*)smraw;                 // [2][256][72]
    float* pb  = smraw + SM_HBF;              // [8][16][68]

    const int tid  = threadIdx.x;
    const int u0   = blockIdx.x * 4;
    const int wid  = tid >> 5;
    const int lane = tid & 31;
    const int g    = lane >> 2;
    const int t4   = lane & 3;
    const int qbase = wid * 4;
    // update mapping
    const int ub  = tid & 63;
    const int uug = tid >> 6;                  // 0..3
    const int myu = u0 + uug;
    float creg = c_init[ub * UU + myu];

    // ---- one-time: build W fragments in registers (A operand, row-major m16k16) ----
    u32 wa[2][4][4];   // [part][q local][reg]
#pragma unroll
    for (int ql = 0; ql < 4; ++ql) {
#pragma unroll
        for (int r = 0; r < 4; ++r) {
            int m  = g + ((r & 1) ? 8 : 0);
            int kk = (qbase + ql) * 16 + 2 * t4 + ((r & 2) ? 8 : 0);
            int cm = (m >> 2) * 512 + u0 + (m & 3);
            float v0 = Wh[(size_t)kk * G4U + cm];
            float v1 = Wh[(size_t)(kk + 1) * G4U + cm];
            unsigned short h0, l0, h1, l1;
            bf16_split(v0, h0, l0);
            bf16_split(v1, h1, l1);
            wa[0][ql][r] = pack16(h0, h1);
            wa[1][ql][r] = pack16(l0, l1);
        }
    }

    for (int t = 0; t < TT; ++t) {
        // ---- stage h(t-1) frag words into smem ----
        if (t == 0) {
            // build frags from fp32 h_init [b][512]
            for (int i = 0; i < 128; ++i) {
                int w = tid + i * 256;            // 0..32767
                int p = w >> 14;
                int rem = w & 16383;
                int k2 = rem >> 6;
                int b  = rem & 63;
                float2 hv = *(const float2*)(h_init + b * UU + 2 * k2);
                unsigned short h0, l0, h1, l1;
                bf16_split(hv.x, h0, l0);
                bf16_split(hv.y, h1, l1);
                hbf[p * HBF_PLANE + k2 * 72 + b] = p ? pack16(l0, l1) : pack16(h0, h1);
            }
        } else {
            const ulonglong2* src = (const ulonglong2*)(Hf + (size_t)(t - 1) * 32768);
            for (int i = 0; i < 32; ++i) {
                int idx4 = tid + i * 256;          // 0..8191 (16-byte units)
                ulonglong2 v = src[idx4];
                int w0 = idx4 * 4;
                int p  = w0 >> 14;
                int rem = w0 & 16383;
                int k2 = rem >> 6;
                int b  = rem & 63;
                *(ulonglong2*)&hbf[p * HBF_PLANE + k2 * 72 + b] = v;
            }
        }

        // Xg bias terms (coalesced, overlap with mma)
        const float* xp = Xg + ((size_t)t * G4U + u0 + uug) * BB + ub;
        float xgi = xp[0 * 512 * BB];
        float xgj = xp[1 * 512 * BB];
        float xgf = xp[2 * 512 * BB];
        float xgo = xp[3 * 512 * BB];
        __syncthreads();

        // ---- tensor-core GEMM: 4 q-chunks x 8 n-tiles x 3 precision terms ----
        float d[8][4];
#pragma unroll
        for (int j = 0; j < 8; j++)
#pragma unroll
            for (int r = 0; r < 4; r++) d[j][r] = 0.0f;

#pragma unroll
        for (int ql = 0; ql < 4; ++ql) {
            int q = qbase + ql;
            const u32* bh = hbf + (q * 8 + t4) * 72 + g;
            const u32* bl = bh + HBF_PLANE;
#pragma unroll
            for (int j = 0; j < 8; ++j) {
                u32 bh0 = bh[j * 8];
                u32 bh1 = bh[4 * 72 + j * 8];
                u32 bl0 = bl[j * 8];
                u32 bl1 = bl[4 * 72 + j * 8];
                mma_bf16(d[j], wa[0][ql][0], wa[0][ql][1], wa[0][ql][2], wa[0][ql][3], bh0, bh1);
                mma_bf16(d[j], wa[0][ql][0], wa[0][ql][1], wa[0][ql][2], wa[0][ql][3], bl0, bl1);
                mma_bf16(d[j], wa[1][ql][0], wa[1][ql][1], wa[1][ql][2], wa[1][ql][3], bh0, bh1);
            }
        }

        // ---- store per-warp partials ----
        {
            float* pw = pb + wid * 16 * 68;
#pragma unroll
            for (int j = 0; j < 8; ++j) {
                int n = j * 8 + 2 * t4;
                *(float2*)&pw[g * 68 + n]       = make_float2(d[j][0], d[j][1]);
                *(float2*)&pw[(g + 8) * 68 + n] = make_float2(d[j][2], d[j][3]);
            }
        }
        __syncthreads();

        // ---- reduce 8 warps + cell update (every thread owns one (b,u)) ----
        {
            float gs[4];
#pragma unroll
            for (int gate = 0; gate < 4; ++gate) {
                int m = gate * 4 + uug;
                float s = 0.0f;
#pragma unroll
                for (int w = 0; w < 8; ++w)
                    s += pb[(w * 16 + m) * 68 + ub];
                gs[gate] = s;
            }
            float gi = xgi + gs[0];
            float gj = xgj + gs[1];
            float gf = xgf + gs[2];
            float go = xgo + gs[3];
            float cn = fsig(gf + 1.0f) * creg + fsig(gi) * ftanh(gj);
            float hn = fsig(go) * ftanh(cn);
            creg = cn;
            // write frag-format h (bf16 hi/lo, 2-byte stores)
            unsigned short hh, hl;
            bf16_split(hn, hh, hl);
            char* base = (char*)(Hf + (size_t)t * 32768);
            size_t off = ((size_t)(myu >> 1) * 64 + ub) * 4 + (myu & 1) * 2;
            *(unsigned short*)(base + off) = hh;
            *(unsigned short*)(base + 65536 + off) = hl;
            // fp32 copy for next layer's xgemm / projection
            Hbt[(size_t)(ub * TT + t) * UU + myu] = hn;
            if (t == TT - 1) {
                c_fin[ub * UU + myu] = cn;
                h_fin[ub * UU + myu] = hn;
            }
        }
        grid_sync_all();
    }
}

// ---------------- output projection + length mask ----------------
__global__ __launch_bounds__(256) void proj_kernel(
    const float* __restrict__ H, const float* __restrict__ Wo,
    const float* __restrict__ bo, const int* __restrict__ lens,
    float* __restrict__ out)
{
    __shared__ float hs[4][512];
    const int tid = threadIdx.x;
    const int row0 = blockIdx.x * 4;
    for (int idx = tid; idx < 4 * UU; idx += 256)
        hs[idx >> 9][idx & 511] = H[(size_t)row0 * UU + idx];
    __syncthreads();
    const int r = tid >> 6;
    const int c = tid & 63;
    float acc = bo[c];
#pragma unroll 8
    for (int k = 0; k < UU; ++k)
        acc = fmaf(hs[r][k], Wo[k * FF + c], acc);
    const int row = row0 + r;
    const int b = row >> 8;
    const int t = row & 255;
    out[(size_t)row * FF + c] = (t < lens[b]) ? acc : 0.0f;
}

// ---------------- launch ----------------
extern "C" void kernel_launch(void* const* d_in, const int* in_sizes, int n_in,
                              void* d_out, int out_size)
{
    const float* inputs  = (const float*)d_in[0];
    const float* targets = (const float*)d_in[1];
    const int*   tlen    = (const int*)d_in[2];
    const float* eW0 = (const float*)d_in[3];
    const float* eb0 = (const float*)d_in[4];
    const float* eW1 = (const float*)d_in[5];
    const float* eb1 = (const float*)d_in[6];
    const float* dW0 = (const float*)d_in[7];
    const float* db0 = (const float*)d_in[8];
    const float* dW1 = (const float*)d_in[9];
    const float* db1 = (const float*)d_in[10];
    const float* oW  = (const float*)d_in[11];
    const float* ob  = (const float*)d_in[12];
    float* out = (float*)d_out;

    float *Xg, *H0, *H1, *Hf, *zer, *cF, *hF, *cD, *hD;
    cudaGetSymbolAddress((void**)&Xg,  g_Xg);
    cudaGetSymbolAddress((void**)&H0,  g_H0);
    cudaGetSymbolAddress((void**)&H1,  g_H1);
    cudaGetSymbolAddress((void**)&Hf,  g_Ht);
    cudaGetSymbolAddress((void**)&zer, g_zeros);
    cudaGetSymbolAddress((void**)&cF,  g_cF);
    cudaGetSymbolAddress((void**)&hF,  g_hF);
    cudaGetSymbolAddress((void**)&cD,  g_cDump);
    cudaGetSymbolAddress((void**)&hD,  g_hDump);

    cudaFuncSetAttribute(lstm_recur_kernel,
                         cudaFuncAttributeMaxDynamicSharedMemorySize, REC_SMEM);

    dim3 gx(G4U / 64, NROW / 64);   // (32, 256)

    // encoder layer 0
    xgemm_kernel<<<gx, 256>>>(inputs, eW0, eb0, Xg, NROW, G4U, FF);
    lstm_recur_kernel<<<NCTA_REC, 256, REC_SMEM>>>(Xg, eW0 + (size_t)FF * G4U,
                                                   zer, zer, Hf, H0, cF, hF);
    // encoder layer 1
    xgemm_kernel<<<gx, 256>>>(H0, eW1, eb1, Xg, NROW, G4U, UU);
    lstm_recur_kernel<<<NCTA_REC, 256, REC_SMEM>>>(Xg, eW1 + (size_t)UU * G4U,
                                                   zer, zer, Hf, H1,
                                                   cF + BB * UU, hF + BB * UU);
    // decoder layer 0 (init = encoder layer-0 finals)
    xgemm_kernel<<<gx, 256>>>(targets, dW0, db0, Xg, NROW, G4U, FF);
    lstm_recur_kernel<<<NCTA_REC, 256, REC_SMEM>>>(Xg, dW0 + (size_t)FF * G4U,
                                                   cF, hF, Hf, H0, cD, hD);
    // decoder layer 1 (init = encoder layer-1 finals)
    xgemm_kernel<<<gx, 256>>>(H0, dW1, db1, Xg, NROW, G4U, UU);
    lstm_recur_kernel<<<NCTA_REC, 256, REC_SMEM>>>(Xg, dW1 + (size_t)UU * G4U,
                                                   cF + BB * UU, hF + BB * UU,
                                                   Hf, H1, cD, hD);
    // projection + mask
    proj_kernel<<<NROW / 4, 256>>>(H1, oW, ob, tlen, out);
}

// round 8
// speedup vs baseline: 2.7591x; 1.8089x over previous
#include <cuda_runtime.h>
#include <cuda_bf16.h>
#include <math.h>

#define BB 64
#define TT 256
#define FF 64
#define UU 512
#define G4U 2048
#define NROW (BB*TT)

typedef unsigned long long u64;
typedef unsigned int u32;

// ---------------- scratch (device globals) ----------------
__device__ float g_Xg[TT * G4U * BB];      // layer-0 x-gates, [t][col][b] (134 MB)
__device__ float g_H0[NROW * UU];          // sink (encoder h1 fp32, unused)
__device__ float g_H1[NROW * UU];          // decoder h1 fp32 -> projection
__device__ float g_Hf0[TT * 32768];        // layer0 h frag stream [t][p][k2][b]
__device__ float g_Hf1[TT * 32768];        // layer1 h frag stream
__device__ float g_WFx[64 * 8 * 512 * 4];  // prebuilt x-half W1 frags (4 MB)
__device__ float g_zeros[BB * UU];         // stays zero
__device__ float g_cF[2 * BB * UU];        // encoder finals (layer0, layer1)
__device__ float g_hF[2 * BB * UU];
__device__ float g_cD[2 * BB * UU];        // decoder final dumps
__device__ float g_hD[2 * BB * UU];
__device__ unsigned g_barCount = 0;
__device__ unsigned g_barGen = 0;

// ---------------- f32x2 helpers (xgemm) ----------------
__device__ __forceinline__ u64 splat2(float v) {
    u64 r; asm("mov.b64 %0, {%1, %1};" : "=l"(r) : "f"(v)); return r;
}
__device__ __forceinline__ void unpack2(u64 p, float& lo, float& hi) {
    asm("mov.b64 {%0, %1}, %2;" : "=f"(lo), "=f"(hi) : "l"(p));
}
__device__ __forceinline__ u64 ffma2(u64 a, u64 b, u64 c) {
    u64 d; asm("fma.rn.f32x2 %0, %1, %2, %3;" : "=l"(d) : "l"(a), "l"(b), "l"(c)); return d;
}

// ---------------- bf16 split helpers ----------------
__device__ __forceinline__ void bf16_split(float v, unsigned short& hi, unsigned short& lo) {
    __nv_bfloat16 h = __float2bfloat16(v);
    __nv_bfloat16 l = __float2bfloat16(v - __bfloat162float(h));
    hi = __bfloat16_as_ushort(h);
    lo = __bfloat16_as_ushort(l);
}
__device__ __forceinline__ u32 pack16(unsigned short a, unsigned short b) {
    return (u32)a | ((u32)b << 16);
}

// ---------------- mma m16n8k16 bf16 ----------------
__device__ __forceinline__ void mma_bf16(float* d, u32 a0, u32 a1, u32 a2, u32 a3,
                                         u32 b0, u32 b1) {
    asm volatile(
        "mma.sync.aligned.m16n8k16.row.col.f32.bf16.bf16.f32 "
        "{%0,%1,%2,%3}, {%4,%5,%6,%7}, {%8,%9}, {%0,%1,%2,%3};"
        : "+f"(d[0]), "+f"(d[1]), "+f"(d[2]), "+f"(d[3])
        : "r"(a0), "r"(a1), "r"(a2), "r"(a3), "r"(b0), "r"(b1));
}

// ---------------- grid barrier ----------------
__device__ __forceinline__ void grid_sync_all() {
    __syncthreads();
    if (threadIdx.x == 0) {
        __threadfence();
        unsigned gen = *(volatile unsigned*)&g_barGen;
        unsigned arr = atomicAdd(&g_barCount, 1u);
        if (arr == gridDim.x - 1) {
            g_barCount = 0;
            __threadfence();
            atomicAdd(&g_barGen, 1u);
        } else {
            while (*(volatile unsigned*)&g_barGen == gen) { }
        }
        __threadfence();
    }
    __syncthreads();
}

__device__ __forceinline__ float fsig(float x) {
    return __fdividef(1.0f, 1.0f + __expf(-x));
}
__device__ __forceinline__ float ftanh(float x) {
    float t = __expf(2.0f * x);
    return 1.0f - 2.0f * __fdividef(1.0f, t + 1.0f);
}

// ---------------- xgemm (f32x2), writes transposed Xg [t][col][b] ----------------
__global__ __launch_bounds__(256) void xgemm_kernel(
    const float* __restrict__ A, const float* __restrict__ W,
    const float* __restrict__ bias, float* __restrict__ C,
    int M, int N, int K)
{
    __shared__ float As[16][68];
    __shared__ float Bs2[16][136];
    const int tid = threadIdx.x;
    const int bm = blockIdx.y * 64;
    const int bn = blockIdx.x * 64;
    const int tx = tid & 15;
    const int ty = tid >> 4;
    const int lr  = tid >> 2;
    const int lkq = tid & 3;
    const int lk  = tid >> 4;
    const int lnq = tid & 15;

    u64 acc01[4], acc23[4];
#pragma unroll
    for (int j = 0; j < 4; j++) { acc01[j] = 0ull; acc23[j] = 0ull; }

    for (int k0 = 0; k0 < K; k0 += 16) {
        float4 av = *(const float4*)(A + (size_t)(bm + lr) * K + k0 + lkq * 4);
        float4 wv = *(const float4*)(W + (size_t)(k0 + lk) * N + bn + lnq * 4);
        __syncthreads();
        As[lkq*4+0][lr] = av.x; As[lkq*4+1][lr] = av.y;
        As[lkq*4+2][lr] = av.z; As[lkq*4+3][lr] = av.w;
        {
            ulonglong2 s01; s01.x = splat2(wv.x); s01.y = splat2(wv.y);
            ulonglong2 s23; s23.x = splat2(wv.z); s23.y = splat2(wv.w);
            *(ulonglong2*)&Bs2[lk][lnq*8]     = s01;
            *(ulonglong2*)&Bs2[lk][lnq*8 + 4] = s23;
        }
        __syncthreads();
#pragma unroll
        for (int kk = 0; kk < 16; ++kk) {
            ulonglong2 a  = *(const ulonglong2*)&As[kk][ty*4];
            ulonglong2 b0 = *(const ulonglong2*)&Bs2[kk][tx*8];
            ulonglong2 b1 = *(const ulonglong2*)&Bs2[kk][tx*8+4];
            acc01[0] = ffma2(a.x, b0.x, acc01[0]);
            acc01[1] = ffma2(a.x, b0.y, acc01[1]);
            acc01[2] = ffma2(a.x, b1.x, acc01[2]);
            acc01[3] = ffma2(a.x, b1.y, acc01[3]);
            acc23[0] = ffma2(a.y, b0.x, acc23[0]);
            acc23[1] = ffma2(a.y, b0.y, acc23[1]);
            acc23[2] = ffma2(a.y, b1.x, acc23[2]);
            acc23[3] = ffma2(a.y, b1.y, acc23[3]);
        }
    }
    float4 bv = *(const float4*)(bias + bn + tx * 4);
    float rv[4][4];
#pragma unroll
    for (int j = 0; j < 4; j++) {
        unpack2(acc01[j], rv[0][j], rv[1][j]);
        unpack2(acc23[j], rv[2][j], rv[3][j]);
    }
    const float bias4[4] = {bv.x, bv.y, bv.z, bv.w};
#pragma unroll
    for (int i = 0; i < 4; i++) {
        int row = bm + ty * 4 + i;
        int b = row >> 8;
        int t = row & 255;
#pragma unroll
        for (int j = 0; j < 4; j++) {
            int col = bn + tx * 4 + j;
            C[((size_t)t * G4U + col) * BB + b] = rv[i][j] + bias4[j];
        }
    }
}

// ---------------- prep: build x-half W1 fragments ----------------
__global__ __launch_bounds__(256) void prep_wfx_kernel(const float* __restrict__ W1,
                                                       float* __restrict__ WFx)
{
    const int c   = blockIdx.x;        // L1 cta id 0..63
    const int tid = threadIdx.x;
    const int wid = tid >> 5;
    const int lane = tid & 31;
    const int g  = lane >> 2;
    const int t4 = lane & 3;
    const int u0 = c * 8;
    uint4* out = (uint4*)WFx + (size_t)(c * 8 + wid) * 512 + lane;
#pragma unroll
    for (int ql = 0; ql < 4; ++ql) {
        int q = wid * 4 + ql;          // x-part kchunk 0..31
#pragma unroll
        for (int mt = 0; mt < 2; ++mt) {
            u32 hi4[4], lo4[4];
#pragma unroll
            for (int r = 0; r < 4; ++r) {
                int m  = mt * 16 + g + ((r & 1) ? 8 : 0);
                int kk = q * 16 + 2 * t4 + ((r & 2) ? 8 : 0);
                int cm = (m >> 3) * 512 + u0 + (m & 7);
                float v0 = W1[(size_t)kk * G4U + cm];
                float v1 = W1[(size_t)(kk + 1) * G4U + cm];
                unsigned short h0, l0, h1, l1;
                bf16_split(v0, h0, l0);
                bf16_split(v1, h1, l1);
                hi4[r] = pack16(h0, h1);
                lo4[r] = pack16(l0, l1);
            }
            out[((ql * 2 + mt) * 2 + 0) * 32] = make_uint4(hi4[0], hi4[1], hi4[2], hi4[3]);
            out[((ql * 2 + mt) * 2 + 1) * 32] = make_uint4(lo4[0], lo4[1], lo4[2], lo4[3]);
        }
    }
}

// ---------------- fused dual-layer recurrence ----------------
#define HBF_PLANE (256*72)
#define SM_HBF (2*HBF_PLANE)          // u32 words
#define SM_PB  (8*32*68)              // floats
#define REC_SMEM ((SM_HBF + SM_PB) * 4)   // 217,088 B

__device__ __forceinline__ void stage_from_global(u32* hbf, const float* Hf, int t, int tid) {
    const ulonglong2* src = (const ulonglong2*)(Hf + (size_t)t * 32768);
#pragma unroll
    for (int i = 0; i < 32; ++i) {
        int idx4 = tid + i * 256;
        ulonglong2 v = src[idx4];
        int w0 = idx4 * 4;
        int p = w0 >> 14;
        int rem = w0 & 16383;
        int k2 = rem >> 6;
        int b  = rem & 63;
        *(ulonglong2*)&hbf[p * HBF_PLANE + k2 * 72 + b] = v;
    }
}

__device__ __forceinline__ void stage_from_fp32(u32* hbf, const float* hinit, int tid) {
    for (int i = 0; i < 128; ++i) {
        int w = tid + i * 256;
        int p = w >> 14;
        int rem = w & 16383;
        int k2 = rem >> 6;
        int b  = rem & 63;
        float2 hv = *(const float2*)(hinit + b * UU + 2 * k2);
        unsigned short h0, l0, h1, l1;
        bf16_split(hv.x, h0, l0);
        bf16_split(hv.y, h1, l1);
        hbf[p * HBF_PLANE + k2 * 72 + b] = p ? pack16(l0, l1) : pack16(h0, h1);
    }
}

__device__ __forceinline__ void build_wfrags(const float* W, int qbase, int u0, int g, int t4,
                                             u32 wh[4][2][4], u32 wl[4][2][4]) {
#pragma unroll
    for (int ql = 0; ql < 4; ++ql) {
        int q = qbase + ql;
#pragma unroll
        for (int mt = 0; mt < 2; ++mt) {
#pragma unroll
            for (int r = 0; r < 4; ++r) {
                int m  = mt * 16 + g + ((r & 1) ? 8 : 0);
                int kk = q * 16 + 2 * t4 + ((r & 2) ? 8 : 0);
                int cm = (m >> 3) * 512 + u0 + (m & 7);
                float v0 = W[(size_t)kk * G4U + cm];
                float v1 = W[(size_t)(kk + 1) * G4U + cm];
                unsigned short h0, l0, h1, l1;
                bf16_split(v0, h0, l0);
                bf16_split(v1, h1, l1);
                wh[ql][mt][r] = pack16(h0, h1);
                wl[ql][mt][r] = pack16(l0, l1);
            }
        }
    }
}

__device__ __forceinline__ void mma_half_reg(float d[2][8][4], const u32* hbf,
                                             int wid, int g, int t4,
                                             u32 wh[4][2][4], u32 wl[4][2][4]) {
#pragma unroll
    for (int ql = 0; ql < 4; ++ql) {
        int qb = wid * 4 + ql;
        const u32* bh = hbf + (qb * 8 + t4) * 72 + g;
        const u32* bl = bh + HBF_PLANE;
#pragma unroll
        for (int j = 0; j < 8; ++j) {
            u32 bh0 = bh[j * 8];
            u32 bh1 = bh[4 * 72 + j * 8];
            u32 bl0 = bl[j * 8];
            u32 bl1 = bl[4 * 72 + j * 8];
#pragma unroll
            for (int mt = 0; mt < 2; ++mt) {
                mma_bf16(d[mt][j], wh[ql][mt][0], wh[ql][mt][1], wh[ql][mt][2], wh[ql][mt][3], bh0, bh1);
                mma_bf16(d[mt][j], wh[ql][mt][0], wh[ql][mt][1], wh[ql][mt][2], wh[ql][mt][3], bl0, bl1);
                mma_bf16(d[mt][j], wl[ql][mt][0], wl[ql][mt][1], wl[ql][mt][2], wl[ql][mt][3], bh0, bh1);
            }
        }
    }
}

__device__ __forceinline__ void mma_half_stream(float d[2][8][4], const u32* hbf,
                                                const uint4* wf, int wid, int g, int t4) {
#pragma unroll
    for (int ql = 0; ql < 4; ++ql) {
        int qb = wid * 4 + ql;
        const u32* bh = hbf + (qb * 8 + t4) * 72 + g;
        const u32* bl = bh + HBF_PLANE;
        uint4 whi0 = wf[((ql * 2 + 0) * 2 + 0) * 32];
        uint4 wlo0 = wf[((ql * 2 + 0) * 2 + 1) * 32];
        uint4 whi1 = wf[((ql * 2 + 1) * 2 + 0) * 32];
        uint4 wlo1 = wf[((ql * 2 + 1) * 2 + 1) * 32];
#pragma unroll
        for (int j = 0; j < 8; ++j) {
            u32 bh0 = bh[j * 8];
            u32 bh1 = bh[4 * 72 + j * 8];
            u32 bl0 = bl[j * 8];
            u32 bl1 = bl[4 * 72 + j * 8];
            mma_bf16(d[0][j], whi0.x, whi0.y, whi0.z, whi0.w, bh0, bh1);
            mma_bf16(d[0][j], whi0.x, whi0.y, whi0.z, whi0.w, bl0, bl1);
            mma_bf16(d[0][j], wlo0.x, wlo0.y, wlo0.z, wlo0.w, bh0, bh1);
            mma_bf16(d[1][j], whi1.x, whi1.y, whi1.z, whi1.w, bh0, bh1);
            mma_bf16(d[1][j], whi1.x, whi1.y, whi1.z, whi1.w, bl0, bl1);
            mma_bf16(d[1][j], wlo1.x, wlo1.y, wlo1.z, wlo1.w, bh0, bh1);
        }
    }
}

__device__ __forceinline__ void store_pb(float* pb, float d[2][8][4], int wid, int g, int t4) {
    float* pw = pb + wid * 32 * 68;
#pragma unroll
    for (int mt = 0; mt < 2; ++mt) {
#pragma unroll
        for (int j = 0; j < 8; ++j) {
            int n = j * 8 + 2 * t4;
            *(float2*)&pw[(mt * 16 + g) * 68 + n]     = make_float2(d[mt][j][0], d[mt][j][1]);
            *(float2*)&pw[(mt * 16 + g + 8) * 68 + n] = make_float2(d[mt][j][2], d[mt][j][3]);
        }
    }
}

__device__ __forceinline__ void update_publish(
    const float* pb, const float xb[2][4], float* c, int t,
    float* Hf, float* Hbt, float* c_fin, float* h_fin,
    int u0, int ub, int uug)
{
#pragma unroll
    for (int cell = 0; cell < 2; ++cell) {
        int uu = uug + cell * 4;
        int myu = u0 + uu;
        float gs[4];
#pragma unroll
        for (int gate = 0; gate < 4; ++gate) {
            int m = gate * 8 + uu;
            float s = 0.0f;
#pragma unroll
            for (int w = 0; w < 8; ++w)
                s += pb[(w * 32 + m) * 68 + ub];
            gs[gate] = s + xb[cell][gate];
        }
        float cn = fsig(gs[2] + 1.0f) * c[cell] + fsig(gs[0]) * ftanh(gs[1]);
        float hn = fsig(gs[3]) * ftanh(cn);
        c[cell] = cn;
        unsigned short hh, hl;
        bf16_split(hn, hh, hl);
        char* base = (char*)(Hf + (size_t)t * 32768);
        size_t off = ((size_t)(myu >> 1) * 64 + ub) * 4 + (size_t)(myu & 1) * 2;
        *(unsigned short*)(base + off) = hh;
        *(unsigned short*)(base + 65536 + off) = hl;
        if (Hbt) Hbt[(size_t)(ub * TT + t) * UU + myu] = hn;
        if (t == TT - 1) {
            c_fin[ub * UU + myu] = cn;
            h_fin[ub * UU + myu] = hn;
        }
    }
}

__global__ __launch_bounds__(256) void lstm_fused_kernel(
    const float* __restrict__ Xg,    // layer0 x-gates [t][col][b]
    const float* __restrict__ W0h,   // layer0 W h-part (512 rows)
    const float* __restrict__ W1,    // full layer1 W (1024 rows)
    const float* __restrict__ b1,    // layer1 bias
    const float* __restrict__ WFx,   // prebuilt x-half frags
    const float* __restrict__ c0i, const float* __restrict__ h0i,
    const float* __restrict__ c1i, const float* __restrict__ h1i,
    float* __restrict__ Hf0, float* __restrict__ Hf1,
    float* __restrict__ Hbt,
    float* __restrict__ c0f, float* __restrict__ h0f,
    float* __restrict__ c1f, float* __restrict__ h1f)
{
    extern __shared__ float smraw[];
    u32*   hbf = (u32*)smraw;
    float* pb  = smraw + SM_HBF;

    const int tid  = threadIdx.x;
    const int wid  = tid >> 5;
    const int lane = tid & 31;
    const int g    = lane >> 2;
    const int t4   = lane & 3;
    const bool isL1 = blockIdx.x >= 64;
    const int cta  = isL1 ? blockIdx.x - 64 : blockIdx.x;
    const int u0   = cta * 8;
    const int ub   = tid & 63;
    const int uug  = tid >> 6;

    float c[2];
    {
        const float* ci = isL1 ? c1i : c0i;
        c[0] = ci[ub * UU + u0 + uug];
        c[1] = ci[ub * UU + u0 + uug + 4];
    }

    float xbias[2][4];
    if (isL1) {
#pragma unroll
        for (int cell = 0; cell < 2; ++cell)
#pragma unroll
            for (int gate = 0; gate < 4; ++gate)
                xbias[cell][gate] = b1[gate * 512 + u0 + uug + cell * 4];
    }

    u32 wh[4][2][4], wl[4][2][4];
    if (!isL1) build_wfrags(W0h, wid * 4, u0, g, t4, wh, wl);
    else       build_wfrags(W1, 32 + wid * 4, u0, g, t4, wh, wl);

    const uint4* wf = (const uint4*)WFx + (size_t)(cta * 8 + wid) * 512 + lane;

    for (int r = 0; r <= TT; ++r) {
        if (!isL1) {
            if (r < TT) {
                int t = r;
                float xb[2][4];
#pragma unroll
                for (int cell = 0; cell < 2; ++cell)
#pragma unroll
                    for (int gate = 0; gate < 4; ++gate)
                        xb[cell][gate] = Xg[((size_t)t * G4U + gate * 512 + u0 + uug + cell * 4) * BB + ub];
                if (t == 0) stage_from_fp32(hbf, h0i, tid);
                else        stage_from_global(hbf, Hf0, t - 1, tid);
                __syncthreads();
                float d[2][8][4];
#pragma unroll
                for (int mt = 0; mt < 2; ++mt)
#pragma unroll
                    for (int j = 0; j < 8; ++j)
#pragma unroll
                        for (int k = 0; k < 4; ++k) d[mt][j][k] = 0.0f;
                mma_half_reg(d, hbf, wid, g, t4, wh, wl);
                store_pb(pb, d, wid, g, t4);
                __syncthreads();
                update_publish(pb, xb, c, t, Hf0, (float*)0, c0f, h0f, u0, ub, uug);
            }
        } else {
            if (r >= 1) {
                int t = r - 1;
                stage_from_global(hbf, Hf0, t, tid);
                __syncthreads();
                float d[2][8][4];
#pragma unroll
                for (int mt = 0; mt < 2; ++mt)
#pragma unroll
                    for (int j = 0; j < 8; ++j)
#pragma unroll
                        for (int k = 0; k < 4; ++k) d[mt][j][k] = 0.0f;
                mma_half_stream(d, hbf, wf, wid, g, t4);
                __syncthreads();
                if (t == 0) stage_from_fp32(hbf, h1i, tid);
                else        stage_from_global(hbf, Hf1, t - 1, tid);
                __syncthreads();
                mma_half_reg(d, hbf, wid, g, t4, wh, wl);
                store_pb(pb, d, wid, g, t4);
                __syncthreads();
                update_publish(pb, xbias, c, t, Hf1, Hbt, c1f, h1f, u0, ub, uug);
            }
        }
        grid_sync_all();
    }
}

// ---------------- projection + mask ----------------
__global__ __launch_bounds__(256) void proj_kernel(
    const float* __restrict__ H, const float* __restrict__ Wo,
    const float* __restrict__ bo, const int* __restrict__ lens,
    float* __restrict__ out)
{
    __shared__ float hs[4][512];
    const int tid = threadIdx.x;
    const int row0 = blockIdx.x * 4;
    for (int idx = tid; idx < 4 * UU; idx += 256)
        hs[idx >> 9][idx & 511] = H[(size_t)row0 * UU + idx];
    __syncthreads();
    const int r = tid >> 6;
    const int cc = tid & 63;
    float acc = bo[cc];
#pragma unroll 8
    for (int k = 0; k < UU; ++k)
        acc = fmaf(hs[r][k], Wo[k * FF + cc], acc);
    const int row = row0 + r;
    const int b = row >> 8;
    const int t = row & 255;
    out[(size_t)row * FF + cc] = (t < lens[b]) ? acc : 0.0f;
}

// ---------------- launch ----------------
extern "C" void kernel_launch(void* const* d_in, const int* in_sizes, int n_in,
                              void* d_out, int out_size)
{
    const float* inputs  = (const float*)d_in[0];
    const float* targets = (const float*)d_in[1];
    const int*   tlen    = (const int*)d_in[2];
    const float* eW0 = (const float*)d_in[3];
    const float* eb0 = (const float*)d_in[4];
    const float* eW1 = (const float*)d_in[5];
    const float* eb1 = (const float*)d_in[6];
    const float* dW0 = (const float*)d_in[7];
    const float* db0 = (const float*)d_in[8];
    const float* dW1 = (const float*)d_in[9];
    const float* db1 = (const float*)d_in[10];
    const float* oW  = (const float*)d_in[11];
    const float* ob  = (const float*)d_in[12];
    float* out = (float*)d_out;

    float *Xg, *H0, *H1, *Hf0, *Hf1, *WFx, *zer, *cF, *hF, *cD, *hD;
    cudaGetSymbolAddress((void**)&Xg,  g_Xg);
    cudaGetSymbolAddress((void**)&H0,  g_H0);
    cudaGetSymbolAddress((void**)&H1,  g_H1);
    cudaGetSymbolAddress((void**)&Hf0, g_Hf0);
    cudaGetSymbolAddress((void**)&Hf1, g_Hf1);
    cudaGetSymbolAddress((void**)&WFx, g_WFx);
    cudaGetSymbolAddress((void**)&zer, g_zeros);
    cudaGetSymbolAddress((void**)&cF,  g_cF);
    cudaGetSymbolAddress((void**)&hF,  g_hF);
    cudaGetSymbolAddress((void**)&cD,  g_cD);
    cudaGetSymbolAddress((void**)&hD,  g_hD);

    cudaFuncSetAttribute(lstm_fused_kernel,
                         cudaFuncAttributeMaxDynamicSharedMemorySize, REC_SMEM);

    dim3 gx(G4U / 64, NROW / 64);

    // ---- encoder ----
    xgemm_kernel<<<gx, 256>>>(inputs, eW0, eb0, Xg, NROW, G4U, FF);
    prep_wfx_kernel<<<64, 256>>>(eW1, WFx);
    lstm_fused_kernel<<<128, 256, REC_SMEM>>>(
        Xg, eW0 + (size_t)FF * G4U, eW1, eb1, WFx,
        zer, zer, zer, zer,
        Hf0, Hf1, H0,
        cF, hF, cF + BB * UU, hF + BB * UU);
    // ---- decoder ----
    xgemm_kernel<<<gx, 256>>>(targets, dW0, db0, Xg, NROW, G4U, FF);
    prep_wfx_kernel<<<64, 256>>>(dW1, WFx);
    lstm_fused_kernel<<<128, 256, REC_SMEM>>>(
        Xg, dW0 + (size_t)FF * G4U, dW1, db1, WFx,
        cF, hF, cF + BB * UU, hF + BB * UU,
        Hf0, Hf1, H1,
        cD, hD, cD + BB * UU, hD + BB * UU);
    // ---- projection ----
    proj_kernel<<<NROW / 4, 256>>>(H1, oW, ob, tlen, out);
}

// round 9
// speedup vs baseline: 2.8638x; 1.0379x over previous
#include <cuda_runtime.h>
#include <cuda_bf16.h>
#include <math.h>

#define BB 64
#define TT 256
#define FF 64
#define UU 512
#define G4U 2048
#define NROW (BB*TT)

typedef unsigned long long u64;
typedef unsigned int u32;

// ---------------- scratch (device globals) ----------------
__device__ float g_Xg[TT * G4U * BB];      // layer-0 x-gates, [t][col][b]
__device__ float g_H0[NROW * UU];          // sink (encoder h1 fp32, unused)
__device__ float g_H1[NROW * UU];          // decoder h1 fp32 -> projection
__device__ float g_Hf0[TT * 32768];        // layer0 h frag stream [t][p][k2][b]
__device__ float g_Hf1[TT * 32768];        // layer1 h frag stream
__device__ float g_WFx[64 * 8 * 512 * 4];  // prebuilt x-half W1 frags (4 MB)
__device__ float g_zeros[BB * UU];
__device__ float g_cF[2 * BB * UU];
__device__ float g_hF[2 * BB * UU];
__device__ float g_cD[2 * BB * UU];
__device__ float g_hD[2 * BB * UU];
__device__ unsigned g_barCount = 0;
__device__ unsigned g_barGen = 0;

// ---------------- f32x2 helpers ----------------
__device__ __forceinline__ u64 splat2(float v) {
    u64 r; asm("mov.b64 %0, {%1, %1};" : "=l"(r) : "f"(v)); return r;
}
__device__ __forceinline__ void unpack2(u64 p, float& lo, float& hi) {
    asm("mov.b64 {%0, %1}, %2;" : "=f"(lo), "=f"(hi) : "l"(p));
}
__device__ __forceinline__ u64 ffma2(u64 a, u64 b, u64 c) {
    u64 d; asm("fma.rn.f32x2 %0, %1, %2, %3;" : "=l"(d) : "l"(a), "l"(b), "l"(c)); return d;
}

// ---------------- bf16 split helpers ----------------
__device__ __forceinline__ void bf16_split(float v, unsigned short& hi, unsigned short& lo) {
    __nv_bfloat16 h = __float2bfloat16(v);
    __nv_bfloat16 l = __float2bfloat16(v - __bfloat162float(h));
    hi = __bfloat16_as_ushort(h);
    lo = __bfloat16_as_ushort(l);
}
__device__ __forceinline__ u32 pack16(unsigned short a, unsigned short b) {
    return (u32)a | ((u32)b << 16);
}

// ---------------- mma m16n8k16 bf16 ----------------
__device__ __forceinline__ void mma_bf16(float* d, u32 a0, u32 a1, u32 a2, u32 a3,
                                         u32 b0, u32 b1) {
    asm volatile(
        "mma.sync.aligned.m16n8k16.row.col.f32.bf16.bf16.f32 "
        "{%0,%1,%2,%3}, {%4,%5,%6,%7}, {%8,%9}, {%0,%1,%2,%3};"
        : "+f"(d[0]), "+f"(d[1]), "+f"(d[2]), "+f"(d[3])
        : "r"(a0), "r"(a1), "r"(a2), "r"(a3), "r"(b0), "r"(b1));
}

// ---------------- grid barrier ----------------
__device__ __forceinline__ void grid_sync_all() {
    __syncthreads();
    if (threadIdx.x == 0) {
        __threadfence();
        unsigned gen = *(volatile unsigned*)&g_barGen;
        unsigned arr = atomicAdd(&g_barCount, 1u);
        if (arr == gridDim.x - 1) {
            g_barCount = 0;
            __threadfence();
            atomicAdd(&g_barGen, 1u);
        } else {
            while (*(volatile unsigned*)&g_barGen == gen) { }
        }
        __threadfence();
    }
    __syncthreads();
}

__device__ __forceinline__ float fsig(float x) {
    return __fdividef(1.0f, 1.0f + __expf(-x));
}
__device__ __forceinline__ float ftanh(float x) {
    float t = __expf(2.0f * x);
    return 1.0f - 2.0f * __fdividef(1.0f, t + 1.0f);
}

// ---------------- xgemm64: K=64, tile = (all 64 b) x (1 t) x (64 cols) ----------------
// A: [b*256+t][64]; C: [t][col][b] with per-col b-runs contiguous -> float4 stores along b.
__global__ __launch_bounds__(256) void xgemm64_kernel(
    const float* __restrict__ A, const float* __restrict__ W,
    const float* __restrict__ bias, float* __restrict__ C)
{
    __shared__ float As[16][68];
    __shared__ float Bs2[16][136];
    const int tid = threadIdx.x;
    const int bn = blockIdx.x * 64;
    const int t  = blockIdx.y;
    const int tx = tid & 15;
    const int ty = tid >> 4;
    const int lr  = tid >> 2;      // b row 0..63
    const int lkq = tid & 3;
    const int lk  = tid >> 4;
    const int lnq = tid & 15;

    u64 acc01[4], acc23[4];
#pragma unroll
    for (int j = 0; j < 4; j++) { acc01[j] = 0ull; acc23[j] = 0ull; }

#pragma unroll
    for (int k0 = 0; k0 < 64; k0 += 16) {
        float4 av = *(const float4*)(A + ((size_t)lr * 256 + t) * 64 + k0 + lkq * 4);
        float4 wv = *(const float4*)(W + (size_t)(k0 + lk) * G4U + bn + lnq * 4);
        __syncthreads();
        As[lkq*4+0][lr] = av.x; As[lkq*4+1][lr] = av.y;
        As[lkq*4+2][lr] = av.z; As[lkq*4+3][lr] = av.w;
        {
            ulonglong2 s01; s01.x = splat2(wv.x); s01.y = splat2(wv.y);
            ulonglong2 s23; s23.x = splat2(wv.z); s23.y = splat2(wv.w);
            *(ulonglong2*)&Bs2[lk][lnq*8]     = s01;
            *(ulonglong2*)&Bs2[lk][lnq*8 + 4] = s23;
        }
        __syncthreads();
#pragma unroll
        for (int kk = 0; kk < 16; ++kk) {
            ulonglong2 a  = *(const ulonglong2*)&As[kk][ty*4];
            ulonglong2 b0 = *(const ulonglong2*)&Bs2[kk][tx*8];
            ulonglong2 b1 = *(const ulonglong2*)&Bs2[kk][tx*8+4];
            acc01[0] = ffma2(a.x, b0.x, acc01[0]);
            acc01[1] = ffma2(a.x, b0.y, acc01[1]);
            acc01[2] = ffma2(a.x, b1.x, acc01[2]);
            acc01[3] = ffma2(a.x, b1.y, acc01[3]);
            acc23[0] = ffma2(a.y, b0.x, acc23[0]);
            acc23[1] = ffma2(a.y, b0.y, acc23[1]);
            acc23[2] = ffma2(a.y, b1.x, acc23[2]);
            acc23[3] = ffma2(a.y, b1.y, acc23[3]);
        }
    }
    float4 bv = *(const float4*)(bias + bn + tx * 4);
    float bias4[4] = {bv.x, bv.y, bv.z, bv.w};
    float rv[4][4];   // rv[i][j]: b = ty*4+i, col = bn+tx*4+j
#pragma unroll
    for (int j = 0; j < 4; j++) {
        unpack2(acc01[j], rv[0][j], rv[1][j]);
        unpack2(acc23[j], rv[2][j], rv[3][j]);
    }
    float* cp = C + (size_t)t * G4U * BB;
#pragma unroll
    for (int j = 0; j < 4; j++) {
        float bj = bias4[j];
        float4 o = make_float4(rv[0][j] + bj, rv[1][j] + bj, rv[2][j] + bj, rv[3][j] + bj);
        *(float4*)(cp + (size_t)(bn + tx * 4 + j) * BB + ty * 4) = o;
    }
}

// ---------------- prep: build x-half W1 fragments ----------------
__global__ __launch_bounds__(256) void prep_wfx_kernel(const float* __restrict__ W1,
                                                       float* __restrict__ WFx)
{
    const int c   = blockIdx.x;
    const int tid = threadIdx.x;
    const int wid = tid >> 5;
    const int lane = tid & 31;
    const int g  = lane >> 2;
    const int t4 = lane & 3;
    const int u0 = c * 8;
    uint4* out = (uint4*)WFx + (size_t)(c * 8 + wid) * 512 + lane;
#pragma unroll
    for (int ql = 0; ql < 4; ++ql) {
        int q = wid * 4 + ql;
#pragma unroll
        for (int mt = 0; mt < 2; ++mt) {
            u32 hi4[4], lo4[4];
#pragma unroll
            for (int r = 0; r < 4; ++r) {
                int m  = mt * 16 + g + ((r & 1) ? 8 : 0);
                int kk = q * 16 + 2 * t4 + ((r & 2) ? 8 : 0);
                int cm = (m >> 3) * 512 + u0 + (m & 7);
                float v0 = W1[(size_t)kk * G4U + cm];
                float v1 = W1[(size_t)(kk + 1) * G4U + cm];
                unsigned short h0, l0, h1, l1;
                bf16_split(v0, h0, l0);
                bf16_split(v1, h1, l1);
                hi4[r] = pack16(h0, h1);
                lo4[r] = pack16(l0, l1);
            }
            out[((ql * 2 + mt) * 2 + 0) * 32] = make_uint4(hi4[0], hi4[1], hi4[2], hi4[3]);
            out[((ql * 2 + mt) * 2 + 1) * 32] = make_uint4(lo4[0], lo4[1], lo4[2], lo4[3]);
        }
    }
}

// ---------------- fused dual-layer recurrence ----------------
#define HBF_PLANE (256*72)
#define SM_HBF (2*HBF_PLANE)
#define SM_PB  (8*32*68)
#define REC_SMEM ((SM_HBF + SM_PB) * 4)   // 217,088 B

__device__ __forceinline__ void stage_from_global(u32* hbf, const float* Hf, int t, int tid) {
    const ulonglong2* src = (const ulonglong2*)(Hf + (size_t)t * 32768);
#pragma unroll
    for (int i = 0; i < 32; ++i) {
        int idx4 = tid + i * 256;
        ulonglong2 v = src[idx4];
        int w0 = idx4 * 4;
        int p = w0 >> 14;
        int rem = w0 & 16383;
        int k2 = rem >> 6;
        int b  = rem & 63;
        *(ulonglong2*)&hbf[p * HBF_PLANE + k2 * 72 + b] = v;
    }
}

__device__ __forceinline__ void stage_from_fp32(u32* hbf, const float* hinit, int tid) {
    for (int i = 0; i < 128; ++i) {
        int w = tid + i * 256;
        int p = w >> 14;
        int rem = w & 16383;
        int k2 = rem >> 6;
        int b  = rem & 63;
        float2 hv = *(const float2*)(hinit + b * UU + 2 * k2);
        unsigned short h0, l0, h1, l1;
        bf16_split(hv.x, h0, l0);
        bf16_split(hv.y, h1, l1);
        hbf[p * HBF_PLANE + k2 * 72 + b] = p ? pack16(l0, l1) : pack16(h0, h1);
    }
}

__device__ __forceinline__ void build_wfrags(const float* W, int qbase, int u0, int g, int t4,
                                             u32 wh[4][2][4], u32 wl[4][2][4]) {
#pragma unroll
    for (int ql = 0; ql < 4; ++ql) {
        int q = qbase + ql;
#pragma unroll
        for (int mt = 0; mt < 2; ++mt) {
#pragma unroll
            for (int r = 0; r < 4; ++r) {
                int m  = mt * 16 + g + ((r & 1) ? 8 : 0);
                int kk = q * 16 + 2 * t4 + ((r & 2) ? 8 : 0);
                int cm = (m >> 3) * 512 + u0 + (m & 7);
                float v0 = W[(size_t)kk * G4U + cm];
                float v1 = W[(size_t)(kk + 1) * G4U + cm];
                unsigned short h0, l0, h1, l1;
                bf16_split(v0, h0, l0);
                bf16_split(v1, h1, l1);
                wh[ql][mt][r] = pack16(h0, h1);
                wl[ql][mt][r] = pack16(l0, l1);
            }
        }
    }
}

__device__ __forceinline__ void mma_half_reg(float d[2][8][4], const u32* hbf,
                                             int wid, int g, int t4,
                                             u32 wh[4][2][4], u32 wl[4][2][4]) {
#pragma unroll
    for (int ql = 0; ql < 4; ++ql) {
        int qb = wid * 4 + ql;
        const u32* bh = hbf + (qb * 8 + t4) * 72 + g;
        const u32* bl = bh + HBF_PLANE;
#pragma unroll
        for (int j = 0; j < 8; ++j) {
            u32 bh0 = bh[j * 8];
            u32 bh1 = bh[4 * 72 + j * 8];
            u32 bl0 = bl[j * 8];
            u32 bl1 = bl[4 * 72 + j * 8];
#pragma unroll
            for (int mt = 0; mt < 2; ++mt) {
                mma_bf16(d[mt][j], wh[ql][mt][0], wh[ql][mt][1], wh[ql][mt][2], wh[ql][mt][3], bh0, bh1);
                mma_bf16(d[mt][j], wh[ql][mt][0], wh[ql][mt][1], wh[ql][mt][2], wh[ql][mt][3], bl0, bl1);
                mma_bf16(d[mt][j], wl[ql][mt][0], wl[ql][mt][1], wl[ql][mt][2], wl[ql][mt][3], bh0, bh1);
            }
        }
    }
}

// x-half mma: B fragments read DIRECTLY from global Hf0[t] (L2-resident broadcast)
__device__ __forceinline__ void mma_x_global(float d[2][8][4], const float* __restrict__ Hf0t,
                                             const uint4* __restrict__ wf,
                                             int wid, int g, int t4) {
    const u32* Hb = (const u32*)Hf0t;
#pragma unroll
    for (int ql = 0; ql < 4; ++ql) {
        int qb = wid * 4 + ql;
        const u32* bh = Hb + (qb * 8 + t4) * 64 + g;
        const u32* bl = bh + 16384;
        uint4 whi0 = wf[((ql * 2 + 0) * 2 + 0) * 32];
        uint4 wlo0 = wf[((ql * 2 + 0) * 2 + 1) * 32];
        uint4 whi1 = wf[((ql * 2 + 1) * 2 + 0) * 32];
        uint4 wlo1 = wf[((ql * 2 + 1) * 2 + 1) * 32];
#pragma unroll
        for (int j = 0; j < 8; ++j) {
            u32 bh0 = __ldg(bh + j * 8);
            u32 bh1 = __ldg(bh + 4 * 64 + j * 8);
            u32 bl0 = __ldg(bl + j * 8);
            u32 bl1 = __ldg(bl + 4 * 64 + j * 8);
            mma_bf16(d[0][j], whi0.x, whi0.y, whi0.z, whi0.w, bh0, bh1);
            mma_bf16(d[0][j], whi0.x, whi0.y, whi0.z, whi0.w, bl0, bl1);
            mma_bf16(d[0][j], wlo0.x, wlo0.y, wlo0.z, wlo0.w, bh0, bh1);
            mma_bf16(d[1][j], whi1.x, whi1.y, whi1.z, whi1.w, bh0, bh1);
            mma_bf16(d[1][j], whi1.x, whi1.y, whi1.z, whi1.w, bl0, bl1);
            mma_bf16(d[1][j], wlo1.x, wlo1.y, wlo1.z, wlo1.w, bh0, bh1);
        }
    }
}

__device__ __forceinline__ void store_pb(float* pb, float d[2][8][4], int wid, int g, int t4) {
    float* pw = pb + wid * 32 * 68;
#pragma unroll
    for (int mt = 0; mt < 2; ++mt) {
#pragma unroll
        for (int j = 0; j < 8; ++j) {
            int n = j * 8 + 2 * t4;
            *(float2*)&pw[(mt * 16 + g) * 68 + n]     = make_float2(d[mt][j][0], d[mt][j][1]);
            *(float2*)&pw[(mt * 16 + g + 8) * 68 + n] = make_float2(d[mt][j][2], d[mt][j][3]);
        }
    }
}

__device__ __forceinline__ void update_publish(
    const float* pb, const float xb[2][4], float* c, int t,
    float* Hf, float* Hbt, float* c_fin, float* h_fin,
    int u0, int ub, int uug)
{
#pragma unroll
    for (int cell = 0; cell < 2; ++cell) {
        int uu = uug + cell * 4;
        int myu = u0 + uu;
        float gs[4];
#pragma unroll
        for (int gate = 0; gate < 4; ++gate) {
            int m = gate * 8 + uu;
            float s = 0.0f;
#pragma unroll
            for (int w = 0; w < 8; ++w)
                s += pb[(w * 32 + m) * 68 + ub];
            gs[gate] = s + xb[cell][gate];
        }
        float cn = fsig(gs[2] + 1.0f) * c[cell] + fsig(gs[0]) * ftanh(gs[1]);
        float hn = fsig(gs[3]) * ftanh(cn);
        c[cell] = cn;
        unsigned short hh, hl;
        bf16_split(hn, hh, hl);
        char* base = (char*)(Hf + (size_t)t * 32768);
        size_t off = ((size_t)(myu >> 1) * 64 + ub) * 4 + (size_t)(myu & 1) * 2;
        *(unsigned short*)(base + off) = hh;
        *(unsigned short*)(base + 65536 + off) = hl;
        if (Hbt) Hbt[(size_t)(ub * TT + t) * UU + myu] = hn;
        if (t == TT - 1) {
            c_fin[ub * UU + myu] = cn;
            h_fin[ub * UU + myu] = hn;
        }
    }
}

__global__ __launch_bounds__(256) void lstm_fused_kernel(
    const float* __restrict__ Xg,
    const float* __restrict__ W0h,
    const float* __restrict__ W1,
    const float* __restrict__ b1,
    const float* __restrict__ WFx,
    const float* __restrict__ c0i, const float* __restrict__ h0i,
    const float* __restrict__ c1i, const float* __restrict__ h1i,
    float* __restrict__ Hf0, float* __restrict__ Hf1,
    float* __restrict__ Hbt,
    float* __restrict__ c0f, float* __restrict__ h0f,
    float* __restrict__ c1f, float* __restrict__ h1f)
{
    extern __shared__ float smraw[];
    u32*   hbf = (u32*)smraw;
    float* pb  = smraw + SM_HBF;

    const int tid  = threadIdx.x;
    const int wid  = tid >> 5;
    const int lane = tid & 31;
    const int g    = lane >> 2;
    const int t4   = lane & 3;
    const bool isL1 = blockIdx.x >= 64;
    const int cta  = isL1 ? blockIdx.x - 64 : blockIdx.x;
    const int u0   = cta * 8;
    const int ub   = tid & 63;
    const int uug  = tid >> 6;

    float c[2];
    {
        const float* ci = isL1 ? c1i : c0i;
        c[0] = ci[ub * UU + u0 + uug];
        c[1] = ci[ub * UU + u0 + uug + 4];
    }

    float xbias[2][4];
    if (isL1) {
#pragma unroll
        for (int cell = 0; cell < 2; ++cell)
#pragma unroll
            for (int gate = 0; gate < 4; ++gate)
                xbias[cell][gate] = b1[gate * 512 + u0 + uug + cell * 4];
    }

    u32 wh[4][2][4], wl[4][2][4];
    if (!isL1) build_wfrags(W0h, wid * 4, u0, g, t4, wh, wl);
    else       build_wfrags(W1, 32 + wid * 4, u0, g, t4, wh, wl);

    const uint4* wf = (const uint4*)WFx + (size_t)(cta * 8 + wid) * 512 + lane;

    for (int r = 0; r <= TT; ++r) {
        if (!isL1) {
            if (r < TT) {
                int t = r;
                float xb[2][4];
#pragma unroll
                for (int cell = 0; cell < 2; ++cell)
#pragma unroll
                    for (int gate = 0; gate < 4; ++gate)
                        xb[cell][gate] = Xg[((size_t)t * G4U + gate * 512 + u0 + uug + cell * 4) * BB + ub];
                if (t == 0) stage_from_fp32(hbf, h0i, tid);
                else        stage_from_global(hbf, Hf0, t - 1, tid);
                __syncthreads();
                float d[2][8][4];
#pragma unroll
                for (int mt = 0; mt < 2; ++mt)
#pragma unroll
                    for (int j = 0; j < 8; ++j)
#pragma unroll
                        for (int k = 0; k < 4; ++k) d[mt][j][k] = 0.0f;
                mma_half_reg(d, hbf, wid, g, t4, wh, wl);
                store_pb(pb, d, wid, g, t4);
                __syncthreads();
                update_publish(pb, xb, c, t, Hf0, (float*)0, c0f, h0f, u0, ub, uug);
            }
        } else {
            if (r >= 1) {
                int t = r - 1;
                // stage h1(t-1) while x-half mma streams B from global Hf0[t]
                if (t == 0) stage_from_fp32(hbf, h1i, tid);
                else        stage_from_global(hbf, Hf1, t - 1, tid);
                float d[2][8][4];
#pragma unroll
                for (int mt = 0; mt < 2; ++mt)
#pragma unroll
                    for (int j = 0; j < 8; ++j)
#pragma unroll
                        for (int k = 0; k < 4; ++k) d[mt][j][k] = 0.0f;
                mma_x_global(d, Hf0 + (size_t)t * 32768, wf, wid, g, t4);
                __syncthreads();
                mma_half_reg(d, hbf, wid, g, t4, wh, wl);
                store_pb(pb, d, wid, g, t4);
                __syncthreads();
                update_publish(pb, xbias, c, t, Hf1, Hbt, c1f, h1f, u0, ub, uug);
            }
        }
        grid_sync_all();
    }
}

// ---------------- projection + mask ----------------
__global__ __launch_bounds__(256) void proj_kernel(
    const float* __restrict__ H, const float* __restrict__ Wo,
    const float* __restrict__ bo, const int* __restrict__ lens,
    float* __restrict__ out)
{
    __shared__ float hs[4][512];
    const int tid = threadIdx.x;
    const int row0 = blockIdx.x * 4;
    for (int idx = tid; idx < 4 * UU; idx += 256)
        hs[idx >> 9][idx & 511] = H[(size_t)row0 * UU + idx];
    __syncthreads();
    const int r = tid >> 6;
    const int cc = tid & 63;
    float acc = bo[cc];
#pragma unroll 8
    for (int k = 0; k < UU; ++k)
        acc = fmaf(hs[r][k], Wo[k * FF + cc], acc);
    const int row = row0 + r;
    const int b = row >> 8;
    const int t = row & 255;
    out[(size_t)row * FF + cc] = (t < lens[b]) ? acc : 0.0f;
}

// ---------------- launch ----------------
extern "C" void kernel_launch(void* const* d_in, const int* in_sizes, int n_in,
                              void* d_out, int out_size)
{
    const float* inputs  = (const float*)d_in[0];
    const float* targets = (const float*)d_in[1];
    const int*   tlen    = (const int*)d_in[2];
    const float* eW0 = (const float*)d_in[3];
    const float* eb0 = (const float*)d_in[4];
    const float* eW1 = (const float*)d_in[5];
    const float* eb1 = (const float*)d_in[6];
    const float* dW0 = (const float*)d_in[7];
    const float* db0 = (const float*)d_in[8];
    const float* dW1 = (const float*)d_in[9];
    const float* db1 = (const float*)d_in[10];
    const float* oW  = (const float*)d_in[11];
    const float* ob  = (const float*)d_in[12];
    float* out = (float*)d_out;

    float *Xg, *H0, *H1, *Hf0, *Hf1, *WFx, *zer, *cF, *hF, *cD, *hD;
    cudaGetSymbolAddress((void**)&Xg,  g_Xg);
    cudaGetSymbolAddress((void**)&H0,  g_H0);
    cudaGetSymbolAddress((void**)&H1,  g_H1);
    cudaGetSymbolAddress((void**)&Hf0, g_Hf0);
    cudaGetSymbolAddress((void**)&Hf1, g_Hf1);
    cudaGetSymbolAddress((void**)&WFx, g_WFx);
    cudaGetSymbolAddress((void**)&zer, g_zeros);
    cudaGetSymbolAddress((void**)&cF,  g_cF);
    cudaGetSymbolAddress((void**)&hF,  g_hF);
    cudaGetSymbolAddress((void**)&cD,  g_cD);
    cudaGetSymbolAddress((void**)&hD,  g_hD);

    cudaFuncSetAttribute(lstm_fused_kernel,
                         cudaFuncAttributeMaxDynamicSharedMemorySize, REC_SMEM);

    dim3 gx(G4U / 64, TT);   // (32, 256)

    // ---- encoder ----
    xgemm64_kernel<<<gx, 256>>>(inputs, eW0, eb0, Xg);
    prep_wfx_kernel<<<64, 256>>>(eW1, WFx);
    lstm_fused_kernel<<<128, 256, REC_SMEM>>>(
        Xg, eW0 + (size_t)FF * G4U, eW1, eb1, WFx,
        zer, zer, zer, zer,
        Hf0, Hf1, H0,
        cF, hF, cF + BB * UU, hF + BB * UU);
    // ---- decoder ----
    xgemm64_kernel<<<gx, 256>>>(targets, dW0, db0, Xg);
    prep_wfx_kernel<<<64, 256>>>(dW1, WFx);
    lstm_fused_kernel<<<128, 256, REC_SMEM>>>(
        Xg, dW0 + (size_t)FF * G4U, dW1, db1, WFx,
        cF, hF, cF + BB * UU, hF + BB * UU,
        Hf0, Hf1, H1,
        cD, hD, cD + BB * UU, hD + BB * UU);
    // ---- projection ----
    proj_kernel<<<NROW / 4, 256>>>(H1, oW, ob, tlen, out);
}

// round 11
// speedup vs baseline: 3.2372x; 1.1304x over previous
#include <cuda_runtime.h>
#include <cuda_bf16.h>
#include <math.h>

#define BB 64
#define TT 256
#define FF 64
#define UU 512
#define G4U 2048
#define NROW (BB*TT)

typedef unsigned long long u64;
typedef unsigned int u32;

// ---------------- scratch (device globals) ----------------
__device__ float g_Xg[TT * G4U * BB];      // layer-0 x-gates, [t][col][b]
__device__ float g_AT[TT * 64 * 64];       // transposed inputs [t][k][b]
__device__ float g_H1[NROW * UU];          // decoder h1 fp32 -> projection
__device__ float g_Hf0[TT * 32768];        // layer0 h frag stream [t][p][k2][b]
__device__ float g_Hf1[TT * 32768];        // layer1 h frag stream
__device__ float g_WFx[64 * 8 * 512 * 4];  // prebuilt x-half W1 frags (4 MB)
__device__ float g_zeros[BB * UU];
__device__ float g_cF[2 * BB * UU];
__device__ float g_hF[2 * BB * UU];
__device__ float g_cD[2 * BB * UU];
__device__ float g_hD[2 * BB * UU];
__device__ unsigned g_cnt0[TT];            // per-step h0 completion counters
__device__ unsigned g_cnt1[TT];            // per-step h1 completion counters

// ---------------- f32x2 helpers ----------------
__device__ __forceinline__ u64 splat2(float v) {
    u64 r; asm("mov.b64 %0, {%1, %1};" : "=l"(r) : "f"(v)); return r;
}
__device__ __forceinline__ void unpack2(u64 p, float& lo, float& hi) {
    asm("mov.b64 {%0, %1}, %2;" : "=f"(lo), "=f"(hi) : "l"(p));
}
__device__ __forceinline__ u64 ffma2(u64 a, u64 b, u64 c) {
    u64 d; asm("fma.rn.f32x2 %0, %1, %2, %3;" : "=l"(d) : "l"(a), "l"(b), "l"(c)); return d;
}

// ---------------- bf16 split helpers ----------------
__device__ __forceinline__ void bf16_split(float v, unsigned short& hi, unsigned short& lo) {
    __nv_bfloat16 h = __float2bfloat16(v);
    __nv_bfloat16 l = __float2bfloat16(v - __bfloat162float(h));
    hi = __bfloat16_as_ushort(h);
    lo = __bfloat16_as_ushort(l);
}
__device__ __forceinline__ u32 pack16(unsigned short a, unsigned short b) {
    return (u32)a | ((u32)b << 16);
}

// ---------------- mma m16n8k16 bf16 ----------------
__device__ __forceinline__ void mma_bf16(float* d, u32 a0, u32 a1, u32 a2, u32 a3,
                                         u32 b0, u32 b1) {
    asm volatile(
        "mma.sync.aligned.m16n8k16.row.col.f32.bf16.bf16.f32 "
        "{%0,%1,%2,%3}, {%4,%5,%6,%7}, {%8,%9}, {%0,%1,%2,%3};"
        : "+f"(d[0]), "+f"(d[1]), "+f"(d[2]), "+f"(d[3])
        : "r"(a0), "r"(a1), "r"(a2), "r"(a3), "r"(b0), "r"(b1));
}

// ---------------- release/acquire step counters ----------------
__device__ __forceinline__ void cnt_arrive(unsigned* p) {
    asm volatile("red.release.gpu.global.add.u32 [%0], %1;" :: "l"(p), "r"(1u) : "memory");
}
__device__ __forceinline__ void cnt_wait(const unsigned* p, unsigned target) {
    unsigned v;
    do {
        asm volatile("ld.acquire.gpu.global.u32 %0, [%1];" : "=r"(v) : "l"(p) : "memory");
    } while (v < target);
}

__device__ __forceinline__ float fsig(float x) {
    return __fdividef(1.0f, 1.0f + __expf(-x));
}
__device__ __forceinline__ float ftanh(float x) {
    float t = __expf(2.0f * x);
    return 1.0f - 2.0f * __fdividef(1.0f, t + 1.0f);
}

// ---------------- reset counters ----------------
__global__ void reset_cnt_kernel() {
    int i = threadIdx.x;
    if (i < TT) { g_cnt0[i] = 0; g_cnt1[i] = 0; }
}

// ---------------- transpose inputs: AT[t][k][b] = in[b][t][k] ----------------
// 64b x 64k tile = 1024 float4; 256 threads x 4 iterations.
__global__ __launch_bounds__(256) void transpose_in_kernel(
    const float* __restrict__ in, float* __restrict__ outT)
{
    __shared__ float tsm[64][68];
    const int t = blockIdx.x;
    const int tid = threadIdx.x;
#pragma unroll
    for (int i = 0; i < 4; ++i) {
        int idx = tid + i * 256;           // 0..1023 float4 units
        int b  = idx >> 4;                 // 16 float4 per b-row
        int kq = idx & 15;
        float4 v = *(const float4*)(in + ((size_t)b * TT + t) * 64 + kq * 4);
        tsm[kq*4+0][b] = v.x; tsm[kq*4+1][b] = v.y;
        tsm[kq*4+2][b] = v.z; tsm[kq*4+3][b] = v.w;
    }
    __syncthreads();
#pragma unroll
    for (int i = 0; i < 4; ++i) {
        int idx = tid + i * 256;
        int k  = idx >> 4;
        int bq = idx & 15;
        float4 o = *(const float4*)&tsm[k][bq*4];
        *(float4*)(outT + ((size_t)t * 64 + k) * 64 + bq * 4) = o;
    }
}

// ---------------- xgemm64 v2: coalesced A loads + wide stores ----------------
// AT: [t][k][b]; C: [t][col][b]
__global__ __launch_bounds__(256) void xgemm64_kernel(
    const float* __restrict__ AT, const float* __restrict__ W,
    const float* __restrict__ bias, float* __restrict__ C)
{
    __shared__ float As[16][68];
    __shared__ float Bs2[16][136];
    const int tid = threadIdx.x;
    const int bn = blockIdx.x * 64;
    const int t  = blockIdx.y;
    const int tx = tid >> 4;     // col quad
    const int ty = tid & 15;     // b quad
    const int lk = tid >> 4;     // load k
    const int lq = tid & 15;     // load quad

    u64 acc01[4], acc23[4];
#pragma unroll
    for (int j = 0; j < 4; j++) { acc01[j] = 0ull; acc23[j] = 0ull; }

#pragma unroll
    for (int k0 = 0; k0 < 64; k0 += 16) {
        float4 av = *(const float4*)(AT + ((size_t)t * 64 + k0 + lk) * 64 + lq * 4);
        float4 wv = *(const float4*)(W + (size_t)(k0 + lk) * G4U + bn + lq * 4);
        __syncthreads();
        *(float4*)&As[lk][lq * 4] = av;
        {
            ulonglong2 s01; s01.x = splat2(wv.x); s01.y = splat2(wv.y);
            ulonglong2 s23; s23.x = splat2(wv.z); s23.y = splat2(wv.w);
            *(ulonglong2*)&Bs2[lk][lq*8]     = s01;
            *(ulonglong2*)&Bs2[lk][lq*8 + 4] = s23;
        }
        __syncthreads();
#pragma unroll
        for (int kk = 0; kk < 16; ++kk) {
            ulonglong2 a  = *(const ulonglong2*)&As[kk][ty*4];
            ulonglong2 b0 = *(const ulonglong2*)&Bs2[kk][tx*8];
            ulonglong2 b1 = *(const ulonglong2*)&Bs2[kk][tx*8+4];
            acc01[0] = ffma2(a.x, b0.x, acc01[0]);
            acc01[1] = ffma2(a.x, b0.y, acc01[1]);
            acc01[2] = ffma2(a.x, b1.x, acc01[2]);
            acc01[3] = ffma2(a.x, b1.y, acc01[3]);
            acc23[0] = ffma2(a.y, b0.x, acc23[0]);
            acc23[1] = ffma2(a.y, b0.y, acc23[1]);
            acc23[2] = ffma2(a.y, b1.x, acc23[2]);
            acc23[3] = ffma2(a.y, b1.y, acc23[3]);
        }
    }
    float4 bv = *(const float4*)(bias + bn + tx * 4);
    float bias4[4] = {bv.x, bv.y, bv.z, bv.w};
    float rv[4][4];
#pragma unroll
    for (int j = 0; j < 4; j++) {
        unpack2(acc01[j], rv[0][j], rv[1][j]);
        unpack2(acc23[j], rv[2][j], rv[3][j]);
    }
    float* cp = C + (size_t)t * G4U * BB;
#pragma unroll
    for (int j = 0; j < 4; j++) {
        float bj = bias4[j];
        float4 o = make_float4(rv[0][j] + bj, rv[1][j] + bj, rv[2][j] + bj, rv[3][j] + bj);
        *(float4*)(cp + (size_t)(bn + tx * 4 + j) * BB + ty * 4) = o;
    }
}

// ---------------- prep: build x-half W1 fragments ----------------
__global__ __launch_bounds__(256) void prep_wfx_kernel(const float* __restrict__ W1,
                                                       float* __restrict__ WFx)
{
    const int c   = blockIdx.x;
    const int tid = threadIdx.x;
    const int wid = tid >> 5;
    const int lane = tid & 31;
    const int g  = lane >> 2;
    const int t4 = lane & 3;
    const int u0 = c * 8;
    uint4* out = (uint4*)WFx + (size_t)(c * 8 + wid) * 512 + lane;
#pragma unroll
    for (int ql = 0; ql < 4; ++ql) {
        int q = wid * 4 + ql;
#pragma unroll
        for (int mt = 0; mt < 2; ++mt) {
            u32 hi4[4], lo4[4];
#pragma unroll
            for (int r = 0; r < 4; ++r) {
                int m  = mt * 16 + g + ((r & 1) ? 8 : 0);
                int kk = q * 16 + 2 * t4 + ((r & 2) ? 8 : 0);
                int cm = (m >> 3) * 512 + u0 + (m & 7);
                float v0 = W1[(size_t)kk * G4U + cm];
                float v1 = W1[(size_t)(kk + 1) * G4U + cm];
                unsigned short h0, l0, h1, l1;
                bf16_split(v0, h0, l0);
                bf16_split(v1, h1, l1);
                hi4[r] = pack16(h0, h1);
                lo4[r] = pack16(l0, l1);
            }
            out[((ql * 2 + mt) * 2 + 0) * 32] = make_uint4(hi4[0], hi4[1], hi4[2], hi4[3]);
            out[((ql * 2 + mt) * 2 + 1) * 32] = make_uint4(lo4[0], lo4[1], lo4[2], lo4[3]);
        }
    }
}

// ---------------- fused dual-layer recurrence (counter-synced) ----------------
#define HBF_PLANE (256*72)
#define SM_HBF (2*HBF_PLANE)
#define SM_PB  (8*32*68)
#define REC_SMEM ((SM_HBF + SM_PB) * 4)   // 217,088 B

__device__ __forceinline__ void stage_from_global(u32* hbf, const float* Hf, int t, int tid) {
    const ulonglong2* src = (const ulonglong2*)(Hf + (size_t)t * 32768);
#pragma unroll
    for (int i = 0; i < 32; ++i) {
        int idx4 = tid + i * 256;
        ulonglong2 v = src[idx4];
        int w0 = idx4 * 4;
        int p = w0 >> 14;
        int rem = w0 & 16383;
        int k2 = rem >> 6;
        int b  = rem & 63;
        *(ulonglong2*)&hbf[p * HBF_PLANE + k2 * 72 + b] = v;
    }
}

__device__ __forceinline__ void stage_from_fp32(u32* hbf, const float* hinit, int tid) {
    for (int i = 0; i < 128; ++i) {
        int w = tid + i * 256;
        int p = w >> 14;
        int rem = w & 16383;
        int k2 = rem >> 6;
        int b  = rem & 63;
        float2 hv = *(const float2*)(hinit + b * UU + 2 * k2);
        unsigned short h0, l0, h1, l1;
        bf16_split(hv.x, h0, l0);
        bf16_split(hv.y, h1, l1);
        hbf[p * HBF_PLANE + k2 * 72 + b] = p ? pack16(l0, l1) : pack16(h0, h1);
    }
}

__device__ __forceinline__ void build_wfrags(const float* W, int qbase, int u0, int g, int t4,
                                             u32 wh[4][2][4], u32 wl[4][2][4]) {
#pragma unroll
    for (int ql = 0; ql < 4; ++ql) {
        int q = qbase + ql;
#pragma unroll
        for (int mt = 0; mt < 2; ++mt) {
#pragma unroll
            for (int r = 0; r < 4; ++r) {
                int m  = mt * 16 + g + ((r & 1) ? 8 : 0);
                int kk = q * 16 + 2 * t4 + ((r & 2) ? 8 : 0);
                int cm = (m >> 3) * 512 + u0 + (m & 7);
                float v0 = W[(size_t)kk * G4U + cm];
                float v1 = W[(size_t)(kk + 1) * G4U + cm];
                unsigned short h0, l0, h1, l1;
                bf16_split(v0, h0, l0);
                bf16_split(v1, h1, l1);
                wh[ql][mt][r] = pack16(h0, h1);
                wl[ql][mt][r] = pack16(l0, l1);
            }
        }
    }
}

__device__ __forceinline__ void mma_half_reg(float d[2][8][4], const u32* hbf,
                                             int wid, int g, int t4,
                                             u32 wh[4][2][4], u32 wl[4][2][4]) {
#pragma unroll
    for (int ql = 0; ql < 4; ++ql) {
        int qb = wid * 4 + ql;
        const u32* bh = hbf + (qb * 8 + t4) * 72 + g;
        const u32* bl = bh + HBF_PLANE;
#pragma unroll
        for (int j = 0; j < 8; ++j) {
            u32 bh0 = bh[j * 8];
            u32 bh1 = bh[4 * 72 + j * 8];
            u32 bl0 = bl[j * 8];
            u32 bl1 = bl[4 * 72 + j * 8];
#pragma unroll
            for (int mt = 0; mt < 2; ++mt) {
                mma_bf16(d[mt][j], wh[ql][mt][0], wh[ql][mt][1], wh[ql][mt][2], wh[ql][mt][3], bh0, bh1);
                mma_bf16(d[mt][j], wh[ql][mt][0], wh[ql][mt][1], wh[ql][mt][2], wh[ql][mt][3], bl0, bl1);
                mma_bf16(d[mt][j], wl[ql][mt][0], wl[ql][mt][1], wl[ql][mt][2], wl[ql][mt][3], bh0, bh1);
            }
        }
    }
}

__device__ __forceinline__ void mma_x_global(float d[2][8][4], const float* __restrict__ Hf0t,
                                             const uint4* __restrict__ wf,
                                             int wid, int g, int t4) {
    const u32* Hb = (const u32*)Hf0t;
#pragma unroll
    for (int ql = 0; ql < 4; ++ql) {
        int qb = wid * 4 + ql;
        const u32* bh = Hb + (qb * 8 + t4) * 64 + g;
        const u32* bl = bh + 16384;
        uint4 whi0 = wf[((ql * 2 + 0) * 2 + 0) * 32];
        uint4 wlo0 = wf[((ql * 2 + 0) * 2 + 1) * 32];
        uint4 whi1 = wf[((ql * 2 + 1) * 2 + 0) * 32];
        uint4 wlo1 = wf[((ql * 2 + 1) * 2 + 1) * 32];
#pragma unroll
        for (int j = 0; j < 8; ++j) {
            u32 bh0 = __ldg(bh + j * 8);
            u32 bh1 = __ldg(bh + 4 * 64 + j * 8);
            u32 bl0 = __ldg(bl + j * 8);
            u32 bl1 = __ldg(bl + 4 * 64 + j * 8);
            mma_bf16(d[0][j], whi0.x, whi0.y, whi0.z, whi0.w, bh0, bh1);
            mma_bf16(d[0][j], whi0.x, whi0.y, whi0.z, whi0.w, bl0, bl1);
            mma_bf16(d[0][j], wlo0.x, wlo0.y, wlo0.z, wlo0.w, bh0, bh1);
            mma_bf16(d[1][j], whi1.x, whi1.y, whi1.z, whi1.w, bh0, bh1);
            mma_bf16(d[1][j], whi1.x, whi1.y, whi1.z, whi1.w, bl0, bl1);
            mma_bf16(d[1][j], wlo1.x, wlo1.y, wlo1.z, wlo1.w, bh0, bh1);
        }
    }
}

__device__ __forceinline__ void store_pb(float* pb, float d[2][8][4], int wid, int g, int t4) {
    float* pw = pb + wid * 32 * 68;
#pragma unroll
    for (int mt = 0; mt < 2; ++mt) {
#pragma unroll
        for (int j = 0; j < 8; ++j) {
            int n = j * 8 + 2 * t4;
            *(float2*)&pw[(mt * 16 + g) * 68 + n]     = make_float2(d[mt][j][0], d[mt][j][1]);
            *(float2*)&pw[(mt * 16 + g + 8) * 68 + n] = make_float2(d[mt][j][2], d[mt][j][3]);
        }
    }
}

__device__ __forceinline__ void update_publish(
    const float* pb, const float xb[2][4], float* c, int t,
    float* Hf, float* Hbt, float* c_fin, float* h_fin,
    int u0, int ub, int uug)
{
#pragma unroll
    for (int cell = 0; cell < 2; ++cell) {
        int uu = uug + cell * 4;
        int myu = u0 + uu;
        float gs[4];
#pragma unroll
        for (int gate = 0; gate < 4; ++gate) {
            int m = gate * 8 + uu;
            float s = 0.0f;
#pragma unroll
            for (int w = 0; w < 8; ++w)
                s += pb[(w * 32 + m) * 68 + ub];
            gs[gate] = s + xb[cell][gate];
        }
        float cn = fsig(gs[2] + 1.0f) * c[cell] + fsig(gs[0]) * ftanh(gs[1]);
        float hn = fsig(gs[3]) * ftanh(cn);
        c[cell] = cn;
        unsigned short hh, hl;
        bf16_split(hn, hh, hl);
        char* base = (char*)(Hf + (size_t)t * 32768);
        size_t off = ((size_t)(myu >> 1) * 64 + ub) * 4 + (size_t)(myu & 1) * 2;
        *(unsigned short*)(base + off) = hh;
        *(unsigned short*)(base + 65536 + off) = hl;
        if (Hbt) Hbt[(size_t)(ub * TT + t) * UU + myu] = hn;
        if (t == TT - 1) {
            c_fin[ub * UU + myu] = cn;
            h_fin[ub * UU + myu] = hn;
        }
    }
}

__global__ __launch_bounds__(256) void lstm_fused_kernel(
    const float* __restrict__ Xg,
    const float* __restrict__ W0h,
    const float* __restrict__ W1,
    const float* __restrict__ b1,
    const float* __restrict__ WFx,
    const float* __restrict__ c0i, const float* __restrict__ h0i,
    const float* __restrict__ c1i, const float* __restrict__ h1i,
    float* __restrict__ Hf0, float* __restrict__ Hf1,
    float* __restrict__ Hbt,
    float* __restrict__ c0f, float* __restrict__ h0f,
    float* __restrict__ c1f, float* __restrict__ h1f)
{
    extern __shared__ float smraw[];
    u32*   hbf = (u32*)smraw;
    float* pb  = smraw + SM_HBF;

    const int tid  = threadIdx.x;
    const int wid  = tid >> 5;
    const int lane = tid & 31;
    const int g    = lane >> 2;
    const int t4   = lane & 3;
    const bool isL1 = blockIdx.x >= 64;
    const int cta  = isL1 ? blockIdx.x - 64 : blockIdx.x;
    const int u0   = cta * 8;
    const int ub   = tid & 63;
    const int uug  = tid >> 6;

    float c[2];
    {
        const float* ci = isL1 ? c1i : c0i;
        c[0] = ci[ub * UU + u0 + uug];
        c[1] = ci[ub * UU + u0 + uug + 4];
    }

    u32 wh[4][2][4], wl[4][2][4];
    if (!isL1) build_wfrags(W0h, wid * 4, u0, g, t4, wh, wl);
    else       build_wfrags(W1, 32 + wid * 4, u0, g, t4, wh, wl);

    if (!isL1) {
        // ---------------- layer 0: self-paced chain on cnt0 ----------------
        for (int t = 0; t < TT; ++t) {
            float xb[2][4];
#pragma unroll
            for (int cell = 0; cell < 2; ++cell)
#pragma unroll
                for (int gate = 0; gate < 4; ++gate)
                    xb[cell][gate] = Xg[((size_t)t * G4U + gate * 512 + u0 + uug + cell * 4) * BB + ub];
            if (t > 0) {
                if (tid == 0) cnt_wait(&g_cnt0[t - 1], 64);
                __syncthreads();
                stage_from_global(hbf, Hf0, t - 1, tid);
            } else {
                stage_from_fp32(hbf, h0i, tid);
            }
            __syncthreads();
            float d[2][8][4];
#pragma unroll
            for (int mt = 0; mt < 2; ++mt)
#pragma unroll
                for (int j = 0; j < 8; ++j)
#pragma unroll
                    for (int k = 0; k < 4; ++k) d[mt][j][k] = 0.0f;
            mma_half_reg(d, hbf, wid, g, t4, wh, wl);
            store_pb(pb, d, wid, g, t4);
            __syncthreads();
            update_publish(pb, xb, c, t, Hf0, (float*)0, c0f, h0f, u0, ub, uug);
            __syncthreads();
            if (tid == 0) cnt_arrive(&g_cnt0[t]);
        }
    } else {
        // ---------------- layer 1: trails on cnt0[t] and cnt1[t-1] ----------------
        float xbias[2][4];
#pragma unroll
        for (int cell = 0; cell < 2; ++cell)
#pragma unroll
            for (int gate = 0; gate < 4; ++gate)
                xbias[cell][gate] = b1[gate * 512 + u0 + uug + cell * 4];
        const uint4* wf = (const uint4*)WFx + (size_t)(cta * 8 + wid) * 512 + lane;

        for (int t = 0; t < TT; ++t) {
            if (tid == 0) {
                if (t > 0) cnt_wait(&g_cnt1[t - 1], 64);
                cnt_wait(&g_cnt0[t], 64);
            }
            __syncthreads();
            if (t == 0) stage_from_fp32(hbf, h1i, tid);
            else        stage_from_global(hbf, Hf1, t - 1, tid);
            float d[2][8][4];
#pragma unroll
            for (int mt = 0; mt < 2; ++mt)
#pragma unroll
                for (int j = 0; j < 8; ++j)
#pragma unroll
                    for (int k = 0; k < 4; ++k) d[mt][j][k] = 0.0f;
            mma_x_global(d, Hf0 + (size_t)t * 32768, wf, wid, g, t4);
            __syncthreads();
            mma_half_reg(d, hbf, wid, g, t4, wh, wl);
            store_pb(pb, d, wid, g, t4);
            __syncthreads();
            update_publish(pb, xbias, c, t, Hf1, Hbt, c1f, h1f, u0, ub, uug);
            __syncthreads();
            if (tid == 0) cnt_arrive(&g_cnt1[t]);
        }
    }
}

// ---------------- projection + mask ----------------
__global__ __launch_bounds__(256) void proj_kernel(
    const float* __restrict__ H, const float* __restrict__ Wo,
    const float* __restrict__ bo, const int* __restrict__ lens,
    float* __restrict__ out)
{
    __shared__ float hs[4][512];
    const int tid = threadIdx.x;
    const int row0 = blockIdx.x * 4;
    for (int idx = tid; idx < 4 * UU; idx += 256)
        hs[idx >> 9][idx & 511] = H[(size_t)row0 * UU + idx];
    __syncthreads();
    const int r = tid >> 6;
    const int cc = tid & 63;
    float acc = bo[cc];
#pragma unroll 8
    for (int k = 0; k < UU; ++k)
        acc = fmaf(hs[r][k], Wo[k * FF + cc], acc);
    const int row = row0 + r;
    const int b = row >> 8;
    const int t = row & 255;
    out[(size_t)row * FF + cc] = (t < lens[b]) ? acc : 0.0f;
}

// ---------------- launch ----------------
extern "C" void kernel_launch(void* const* d_in, const int* in_sizes, int n_in,
                              void* d_out, int out_size)
{
    const float* inputs  = (const float*)d_in[0];
    const float* targets = (const float*)d_in[1];
    const int*   tlen    = (const int*)d_in[2];
    const float* eW0 = (const float*)d_in[3];
    const float* eb0 = (const float*)d_in[4];
    const float* eW1 = (const float*)d_in[5];
    const float* eb1 = (const float*)d_in[6];
    const float* dW0 = (const float*)d_in[7];
    const float* db0 = (const float*)d_in[8];
    const float* dW1 = (const float*)d_in[9];
    const float* db1 = (const float*)d_in[10];
    const float* oW  = (const float*)d_in[11];
    const float* ob  = (const float*)d_in[12];
    float* out = (float*)d_out;

    float *Xg, *AT, *H1, *Hf0, *Hf1, *WFx, *zer, *cF, *hF, *cD, *hD;
    cudaGetSymbolAddress((void**)&Xg,  g_Xg);
    cudaGetSymbolAddress((void**)&AT,  g_AT);
    cudaGetSymbolAddress((void**)&H1,  g_H1);
    cudaGetSymbolAddress((void**)&Hf0, g_Hf0);
    cudaGetSymbolAddress((void**)&Hf1, g_Hf1);
    cudaGetSymbolAddress((void**)&WFx, g_WFx);
    cudaGetSymbolAddress((void**)&zer, g_zeros);
    cudaGetSymbolAddress((void**)&cF,  g_cF);
    cudaGetSymbolAddress((void**)&hF,  g_hF);
    cudaGetSymbolAddress((void**)&cD,  g_cD);
    cudaGetSymbolAddress((void**)&hD,  g_hD);

    cudaFuncSetAttribute(lstm_fused_kernel,
                         cudaFuncAttributeMaxDynamicSharedMemorySize, REC_SMEM);

    dim3 gx(G4U / 64, TT);   // (32, 256)

    // ---- encoder ----
    reset_cnt_kernel<<<1, 256>>>();
    transpose_in_kernel<<<TT, 256>>>(inputs, AT);
    xgemm64_kernel<<<gx, 256>>>(AT, eW0, eb0, Xg);
    prep_wfx_kernel<<<64, 256>>>(eW1, WFx);
    lstm_fused_kernel<<<128, 256, REC_SMEM>>>(
        Xg, eW0 + (size_t)FF * G4U, eW1, eb1, WFx,
        zer, zer, zer, zer,
        Hf0, Hf1, (float*)0,
        cF, hF, cF + BB * UU, hF + BB * UU);
    // ---- decoder ----
    reset_cnt_kernel<<<1, 256>>>();
    transpose_in_kernel<<<TT, 256>>>(targets, AT);
    xgemm64_kernel<<<gx, 256>>>(AT, dW0, db0, Xg);
    prep_wfx_kernel<<<64, 256>>>(dW1, WFx);
    lstm_fused_kernel<<<128, 256, REC_SMEM>>>(
        Xg, dW0 + (size_t)FF * G4U, dW1, db1, WFx,
        cF, hF, cF + BB * UU, hF + BB * UU,
        Hf0, Hf1, H1,
        cD, hD, cD + BB * UU, hD + BB * UU);
    // ---- projection ----
    proj_kernel<<<NROW / 4, 256>>>(H1, oW, ob, tlen, out);
}

// round 17
// speedup vs baseline: 3.2918x; 1.0169x over previous
#include <cuda_runtime.h>
#include <cuda_bf16.h>
#include <math.h>

#define BB 64
#define TT 256
#define FF 64
#define UU 512
#define G4U 2048
#define NROW (BB*TT)

typedef unsigned long long u64;
typedef unsigned int u32;

// ---------------- scratch (device globals) ----------------
__device__ float g_Xg[TT * G4U * BB];      // layer-0 x-gates, [t][col][b]
__device__ float g_AT[TT * 64 * 64];       // transposed inputs [t][k][b]
__device__ float g_H1[NROW * UU];          // decoder h1 fp32 -> projection
__device__ float g_Hf0[TT * 32768];        // layer0 h frag stream [t][p][k2][b]
__device__ float g_Hf1[TT * 32768];        // layer1 h frag stream
__device__ float g_WFx[64 * 8 * 512 * 4];  // prebuilt x-half W1 frags (4 MB)
__device__ float g_zeros[BB * UU];
__device__ float g_cF[2 * BB * UU];
__device__ float g_hF[2 * BB * UU];
__device__ float g_cD[2 * BB * UU];
__device__ float g_hD[2 * BB * UU];
__device__ unsigned g_cnt0[TT];            // per-step h0 completion counters
__device__ unsigned g_cnt1[TT];            // per-step h1 completion counters

// ---------------- f32x2 helpers ----------------
__device__ __forceinline__ u64 splat2(float v) {
    u64 r; asm("mov.b64 %0, {%1, %1};" : "=l"(r) : "f"(v)); return r;
}
__device__ __forceinline__ void unpack2(u64 p, float& lo, float& hi) {
    asm("mov.b64 {%0, %1}, %2;" : "=f"(lo), "=f"(hi) : "l"(p));
}
__device__ __forceinline__ u64 ffma2(u64 a, u64 b, u64 c) {
    u64 d; asm("fma.rn.f32x2 %0, %1, %2, %3;" : "=l"(d) : "l"(a), "l"(b), "l"(c)); return d;
}

// ---------------- bf16 split helpers ----------------
__device__ __forceinline__ void bf16_split(float v, unsigned short& hi, unsigned short& lo) {
    __nv_bfloat16 h = __float2bfloat16(v);
    __nv_bfloat16 l = __float2bfloat16(v - __bfloat162float(h));
    hi = __bfloat16_as_ushort(h);
    lo = __bfloat16_as_ushort(l);
}
__device__ __forceinline__ u32 pack16(unsigned short a, unsigned short b) {
    return (u32)a | ((u32)b << 16);
}

// ---------------- mma m16n8k16 bf16 ----------------
__device__ __forceinline__ void mma_bf16(float* d, u32 a0, u32 a1, u32 a2, u32 a3,
                                         u32 b0, u32 b1) {
    asm volatile(
        "mma.sync.aligned.m16n8k16.row.col.f32.bf16.bf16.f32 "
        "{%0,%1,%2,%3}, {%4,%5,%6,%7}, {%8,%9}, {%0,%1,%2,%3};"
        : "+f"(d[0]), "+f"(d[1]), "+f"(d[2]), "+f"(d[3])
        : "r"(a0), "r"(a1), "r"(a2), "r"(a3), "r"(b0), "r"(b1));
}

// ---------------- release/acquire step counters ----------------
__device__ __forceinline__ void cnt_arrive(unsigned* p) {
    asm volatile("red.release.gpu.global.add.u32 [%0], %1;" :: "l"(p), "r"(1u) : "memory");
}
__device__ __forceinline__ void cnt_wait(const unsigned* p, unsigned target) {
    unsigned v;
    do {
        asm volatile("ld.acquire.gpu.global.u32 %0, [%1];" : "=r"(v) : "l"(p) : "memory");
    } while (v < target);
}

__device__ __forceinline__ float fsig(float x) {
    return __fdividef(1.0f, 1.0f + __expf(-x));
}
__device__ __forceinline__ float ftanh(float x) {
    float t = __expf(2.0f * x);
    return 1.0f - 2.0f * __fdividef(1.0f, t + 1.0f);
}

// ---------------- reset counters ----------------
__global__ void reset_cnt_kernel() {
    int i = threadIdx.x;
    if (i < TT) { g_cnt0[i] = 0; g_cnt1[i] = 0; }
}

// ---------------- transpose inputs: AT[t][k][b] = in[b][t][k] ----------------
__global__ __launch_bounds__(256) void transpose_in_kernel(
    const float* __restrict__ in, float* __restrict__ outT)
{
    __shared__ float tsm[64][68];
    const int t = blockIdx.x;
    const int tid = threadIdx.x;
#pragma unroll
    for (int i = 0; i < 4; ++i) {
        int idx = tid + i * 256;
        int b  = idx >> 4;
        int kq = idx & 15;
        float4 v = *(const float4*)(in + ((size_t)b * TT + t) * 64 + kq * 4);
        tsm[kq*4+0][b] = v.x; tsm[kq*4+1][b] = v.y;
        tsm[kq*4+2][b] = v.z; tsm[kq*4+3][b] = v.w;
    }
    __syncthreads();
#pragma unroll
    for (int i = 0; i < 4; ++i) {
        int idx = tid + i * 256;
        int k  = idx >> 4;
        int bq = idx & 15;
        float4 o = *(const float4*)&tsm[k][bq*4];
        *(float4*)(outT + ((size_t)t * 64 + k) * 64 + bq * 4) = o;
    }
}

// ---------------- xgemm64: coalesced A loads + wide stores ----------------
__global__ __launch_bounds__(256) void xgemm64_kernel(
    const float* __restrict__ AT, const float* __restrict__ W,
    const float* __restrict__ bias, float* __restrict__ C)
{
    __shared__ float As[16][68];
    __shared__ float Bs2[16][136];
    const int tid = threadIdx.x;
    const int bn = blockIdx.x * 64;
    const int t  = blockIdx.y;
    const int tx = tid >> 4;
    const int ty = tid & 15;
    const int lk = tid >> 4;
    const int lq = tid & 15;

    u64 acc01[4], acc23[4];
#pragma unroll
    for (int j = 0; j < 4; j++) { acc01[j] = 0ull; acc23[j] = 0ull; }

#pragma unroll
    for (int k0 = 0; k0 < 64; k0 += 16) {
        float4 av = *(const float4*)(AT + ((size_t)t * 64 + k0 + lk) * 64 + lq * 4);
        float4 wv = *(const float4*)(W + (size_t)(k0 + lk) * G4U + bn + lq * 4);
        __syncthreads();
        *(float4*)&As[lk][lq * 4] = av;
        {
            ulonglong2 s01; s01.x = splat2(wv.x); s01.y = splat2(wv.y);
            ulonglong2 s23; s23.x = splat2(wv.z); s23.y = splat2(wv.w);
            *(ulonglong2*)&Bs2[lk][lq*8]     = s01;
            *(ulonglong2*)&Bs2[lk][lq*8 + 4] = s23;
        }
        __syncthreads();
#pragma unroll
        for (int kk = 0; kk < 16; ++kk) {
            ulonglong2 a  = *(const ulonglong2*)&As[kk][ty*4];
            ulonglong2 b0 = *(const ulonglong2*)&Bs2[kk][tx*8];
            ulonglong2 b1 = *(const ulonglong2*)&Bs2[kk][tx*8+4];
            acc01[0] = ffma2(a.x, b0.x, acc01[0]);
            acc01[1] = ffma2(a.x, b0.y, acc01[1]);
            acc01[2] = ffma2(a.x, b1.x, acc01[2]);
            acc01[3] = ffma2(a.x, b1.y, acc01[3]);
            acc23[0] = ffma2(a.y, b0.x, acc23[0]);
            acc23[1] = ffma2(a.y, b0.y, acc23[1]);
            acc23[2] = ffma2(a.y, b1.x, acc23[2]);
            acc23[3] = ffma2(a.y, b1.y, acc23[3]);
        }
    }
    float4 bv = *(const float4*)(bias + bn + tx * 4);
    float bias4[4] = {bv.x, bv.y, bv.z, bv.w};
    float rv[4][4];
#pragma unroll
    for (int j = 0; j < 4; j++) {
        unpack2(acc01[j], rv[0][j], rv[1][j]);
        unpack2(acc23[j], rv[2][j], rv[3][j]);
    }
    float* cp = C + (size_t)t * G4U * BB;
#pragma unroll
    for (int j = 0; j < 4; j++) {
        float bj = bias4[j];
        float4 o = make_float4(rv[0][j] + bj, rv[1][j] + bj, rv[2][j] + bj, rv[3][j] + bj);
        *(float4*)(cp + (size_t)(bn + tx * 4 + j) * BB + ty * 4) = o;
    }
}

// ---------------- prep: build x-half W1 fragments ----------------
__global__ __launch_bounds__(256) void prep_wfx_kernel(const float* __restrict__ W1,
                                                       float* __restrict__ WFx)
{
    const int c   = blockIdx.x;
    const int tid = threadIdx.x;
    const int wid = tid >> 5;
    const int lane = tid & 31;
    const int g  = lane >> 2;
    const int t4 = lane & 3;
    const int u0 = c * 8;
    uint4* out = (uint4*)WFx + (size_t)(c * 8 + wid) * 512 + lane;
#pragma unroll
    for (int ql = 0; ql < 4; ++ql) {
        int q = wid * 4 + ql;
#pragma unroll
        for (int mt = 0; mt < 2; ++mt) {
            u32 hi4[4], lo4[4];
#pragma unroll
            for (int r = 0; r < 4; ++r) {
                int m  = mt * 16 + g + ((r & 1) ? 8 : 0);
                int kk = q * 16 + 2 * t4 + ((r & 2) ? 8 : 0);
                int cm = (m >> 3) * 512 + u0 + (m & 7);
                float v0 = W1[(size_t)kk * G4U + cm];
                float v1 = W1[(size_t)(kk + 1) * G4U + cm];
                unsigned short h0, l0, h1, l1;
                bf16_split(v0, h0, l0);
                bf16_split(v1, h1, l1);
                hi4[r] = pack16(h0, h1);
                lo4[r] = pack16(l0, l1);
            }
            out[((ql * 2 + mt) * 2 + 0) * 32] = make_uint4(hi4[0], hi4[1], hi4[2], hi4[3]);
            out[((ql * 2 + mt) * 2 + 1) * 32] = make_uint4(lo4[0], lo4[1], lo4[2], lo4[3]);
        }
    }
}

// ---------------- fused dual-layer recurrence (counter-synced) ----------------
#define HBF_PLANE (256*72)
#define SM_HBF (2*HBF_PLANE)
#define SM_PB  (8*32*68)
#define REC_SMEM ((SM_HBF + SM_PB) * 4)   // 217,088 B

__device__ __forceinline__ void stage_from_global(u32* hbf, const float* Hf, int t, int tid) {
    const ulonglong2* src = (const ulonglong2*)(Hf + (size_t)t * 32768);
#pragma unroll
    for (int i = 0; i < 32; ++i) {
        int idx4 = tid + i * 256;
        ulonglong2 v = src[idx4];
        int w0 = idx4 * 4;
        int p = w0 >> 14;
        int rem = w0 & 16383;
        int k2 = rem >> 6;
        int b  = rem & 63;
        *(ulonglong2*)&hbf[p * HBF_PLANE + k2 * 72 + b] = v;
    }
}

__device__ __forceinline__ void stage_from_fp32(u32* hbf, const float* hinit, int tid) {
    for (int i = 0; i < 128; ++i) {
        int w = tid + i * 256;
        int p = w >> 14;
        int rem = w & 16383;
        int k2 = rem >> 6;
        int b  = rem & 63;
        float2 hv = *(const float2*)(hinit + b * UU + 2 * k2);
        unsigned short h0, l0, h1, l1;
        bf16_split(hv.x, h0, l0);
        bf16_split(hv.y, h1, l1);
        hbf[p * HBF_PLANE + k2 * 72 + b] = p ? pack16(l0, l1) : pack16(h0, h1);
    }
}

__device__ __forceinline__ void build_wfrags(const float* W, int qbase, int u0, int g, int t4,
                                             u32 wh[4][2][4], u32 wl[4][2][4]) {
#pragma unroll
    for (int ql = 0; ql < 4; ++ql) {
        int q = qbase + ql;
#pragma unroll
        for (int mt = 0; mt < 2; ++mt) {
#pragma unroll
            for (int r = 0; r < 4; ++r) {
                int m  = mt * 16 + g + ((r & 1) ? 8 : 0);
                int kk = q * 16 + 2 * t4 + ((r & 2) ? 8 : 0);
                int cm = (m >> 3) * 512 + u0 + (m & 7);
                float v0 = W[(size_t)kk * G4U + cm];
                float v1 = W[(size_t)(kk + 1) * G4U + cm];
                unsigned short h0, l0, h1, l1;
                bf16_split(v0, h0, l0);
                bf16_split(v1, h1, l1);
                wh[ql][mt][r] = pack16(h0, h1);
                wl[ql][mt][r] = pack16(l0, l1);
            }
        }
    }
}

__device__ __forceinline__ void mma_half_reg(float d[2][8][4], const u32* hbf,
                                             int wid, int g, int t4,
                                             u32 wh[4][2][4], u32 wl[4][2][4]) {
#pragma unroll
    for (int ql = 0; ql < 4; ++ql) {
        int qb = wid * 4 + ql;
        const u32* bh = hbf + (qb * 8 + t4) * 72 + g;
        const u32* bl = bh + HBF_PLANE;
#pragma unroll
        for (int j = 0; j < 8; ++j) {
            u32 bh0 = bh[j * 8];
            u32 bh1 = bh[4 * 72 + j * 8];
            u32 bl0 = bl[j * 8];
            u32 bl1 = bl[4 * 72 + j * 8];
#pragma unroll
            for (int mt = 0; mt < 2; ++mt) {
                mma_bf16(d[mt][j], wh[ql][mt][0], wh[ql][mt][1], wh[ql][mt][2], wh[ql][mt][3], bh0, bh1);
                mma_bf16(d[mt][j], wh[ql][mt][0], wh[ql][mt][1], wh[ql][mt][2], wh[ql][mt][3], bl0, bl1);
                mma_bf16(d[mt][j], wl[ql][mt][0], wl[ql][mt][1], wl[ql][mt][2], wl[ql][mt][3], bh0, bh1);
            }
        }
    }
}

// x-half mma: B fragments read DIRECTLY from global Hf0[t] (L2-resident broadcast)
__device__ __forceinline__ void mma_x_global(float d[2][8][4], const float* __restrict__ Hf0t,
                                             const uint4* __restrict__ wf,
                                             int wid, int g, int t4) {
    const u32* Hb = (const u32*)Hf0t;
#pragma unroll
    for (int ql = 0; ql < 4; ++ql) {
        int qb = wid * 4 + ql;
        const u32* bh = Hb + (qb * 8 + t4) * 64 + g;
        const u32* bl = bh + 16384;
        uint4 whi0 = wf[((ql * 2 + 0) * 2 + 0) * 32];
        uint4 wlo0 = wf[((ql * 2 + 0) * 2 + 1) * 32];
        uint4 whi1 = wf[((ql * 2 + 1) * 2 + 0) * 32];
        uint4 wlo1 = wf[((ql * 2 + 1) * 2 + 1) * 32];
#pragma unroll
        for (int j = 0; j < 8; ++j) {
            u32 bh0 = __ldg(bh + j * 8);
            u32 bh1 = __ldg(bh + 4 * 64 + j * 8);
            u32 bl0 = __ldg(bl + j * 8);
            u32 bl1 = __ldg(bl + 4 * 64 + j * 8);
            mma_bf16(d[0][j], whi0.x, whi0.y, whi0.z, whi0.w, bh0, bh1);
            mma_bf16(d[0][j], whi0.x, whi0.y, whi0.z, whi0.w, bl0, bl1);
            mma_bf16(d[0][j], wlo0.x, wlo0.y, wlo0.z, wlo0.w, bh0, bh1);
            mma_bf16(d[1][j], whi1.x, whi1.y, whi1.z, whi1.w, bh0, bh1);
            mma_bf16(d[1][j], whi1.x, whi1.y, whi1.z, whi1.w, bl0, bl1);
            mma_bf16(d[1][j], wlo1.x, wlo1.y, wlo1.z, wlo1.w, bh0, bh1);
        }
    }
}

__device__ __forceinline__ void store_pb(float* pb, float d[2][8][4], int wid, int g, int t4) {
    float* pw = pb + wid * 32 * 68;
#pragma unroll
    for (int mt = 0; mt < 2; ++mt) {
#pragma unroll
        for (int j = 0; j < 8; ++j) {
            int n = j * 8 + 2 * t4;
            *(float2*)&pw[(mt * 16 + g) * 68 + n]     = make_float2(d[mt][j][0], d[mt][j][1]);
            *(float2*)&pw[(mt * 16 + g + 8) * 68 + n] = make_float2(d[mt][j][2], d[mt][j][3]);
        }
    }
}

__device__ __forceinline__ void update_publish(
    const float* pb, const float xb[2][4], float* c, int t,
    float* Hf, float* Hbt, float* c_fin, float* h_fin,
    int u0, int ub, int uug)
{
#pragma unroll
    for (int cell = 0; cell < 2; ++cell) {
        int uu = uug + cell * 4;
        int myu = u0 + uu;
        float gs[4];
#pragma unroll
        for (int gate = 0; gate < 4; ++gate) {
            int m = gate * 8 + uu;
            float s = 0.0f;
#pragma unroll
            for (int w = 0; w < 8; ++w)
                s += pb[(w * 32 + m) * 68 + ub];
            gs[gate] = s + xb[cell][gate];
        }
        float cn = fsig(gs[2] + 1.0f) * c[cell] + fsig(gs[0]) * ftanh(gs[1]);
        float hn = fsig(gs[3]) * ftanh(cn);
        c[cell] = cn;
        unsigned short hh, hl;
        bf16_split(hn, hh, hl);
        char* base = (char*)(Hf + (size_t)t * 32768);
        size_t off = ((size_t)(myu >> 1) * 64 + ub) * 4 + (size_t)(myu & 1) * 2;
        *(unsigned short*)(base + off) = hh;
        *(unsigned short*)(base + 65536 + off) = hl;
        if (Hbt) Hbt[(size_t)(ub * TT + t) * UU + myu] = hn;
        if (t == TT - 1) {
            c_fin[ub * UU + myu] = cn;
            h_fin[ub * UU + myu] = hn;
        }
    }
}

__global__ __launch_bounds__(256) void lstm_fused_kernel(
    const float* __restrict__ Xg,
    const float* __restrict__ W0h,
    const float* __restrict__ W1,
    const float* __restrict__ b1,
    const float* __restrict__ WFx,
    const float* __restrict__ c0i, const float* __restrict__ h0i,
    const float* __restrict__ c1i, const float* __restrict__ h1i,
    float* __restrict__ Hf0, float* __restrict__ Hf1,
    float* __restrict__ Hbt,
    float* __restrict__ c0f, float* __restrict__ h0f,
    float* __restrict__ c1f, float* __restrict__ h1f)
{
    extern __shared__ float smraw[];
    u32*   hbf = (u32*)smraw;
    float* pb  = smraw + SM_HBF;

    const int tid  = threadIdx.x;
    const int wid  = tid >> 5;
    const int lane = tid & 31;
    const int g    = lane >> 2;
    const int t4   = lane & 3;
    const bool isL1 = blockIdx.x >= 64;
    const int cta  = isL1 ? blockIdx.x - 64 : blockIdx.x;
    const int u0   = cta * 8;
    const int ub   = tid & 63;
    const int uug  = tid >> 6;

    float c[2];
    {
        const float* ci = isL1 ? c1i : c0i;
        c[0] = ci[ub * UU + u0 + uug];
        c[1] = ci[ub * UU + u0 + uug + 4];
    }

    u32 wh[4][2][4], wl[4][2][4];
    if (!isL1) build_wfrags(W0h, wid * 4, u0, g, t4, wh, wl);
    else       build_wfrags(W1, 32 + wid * 4, u0, g, t4, wh, wl);

    if (!isL1) {
        // ---------------- layer 0: self-paced chain on cnt0 ----------------
        for (int t = 0; t < TT; ++t) {
            float xb[2][4];
#pragma unroll
            for (int cell = 0; cell < 2; ++cell)
#pragma unroll
                for (int gate = 0; gate < 4; ++gate)
                    xb[cell][gate] = Xg[((size_t)t * G4U + gate * 512 + u0 + uug + cell * 4) * BB + ub];
            if (t > 0) {
                if (tid == 0) cnt_wait(&g_cnt0[t - 1], 64);
                __syncthreads();
                stage_from_global(hbf, Hf0, t - 1, tid);
            } else {
                stage_from_fp32(hbf, h0i, tid);
            }
            __syncthreads();
            float d[2][8][4];
#pragma unroll
            for (int mt = 0; mt < 2; ++mt)
#pragma unroll
                for (int j = 0; j < 8; ++j)
#pragma unroll
                    for (int k = 0; k < 4; ++k) d[mt][j][k] = 0.0f;
            mma_half_reg(d, hbf, wid, g, t4, wh, wl);
            store_pb(pb, d, wid, g, t4);
            __syncthreads();
            update_publish(pb, xb, c, t, Hf0, (float*)0, c0f, h0f, u0, ub, uug);
            __syncthreads();
            if (tid == 0) cnt_arrive(&g_cnt0[t]);
        }
    } else {
        // ---------------- layer 1: split waits — stage Hf1[t-1] overlaps cnt0[t] spin ----------------
        float xbias[2][4];
#pragma unroll
        for (int cell = 0; cell < 2; ++cell)
#pragma unroll
            for (int gate = 0; gate < 4; ++gate)
                xbias[cell][gate] = b1[gate * 512 + u0 + uug + cell * 4];
        const uint4* wf = (const uint4*)WFx + (size_t)(cta * 8 + wid) * 512 + lane;

        for (int t = 0; t < TT; ++t) {
            if (tid == 0 && t > 0) cnt_wait(&g_cnt1[t - 1], 64);
            __syncthreads();
            if (t == 0) stage_from_fp32(hbf, h1i, tid);
            else        stage_from_global(hbf, Hf1, t - 1, tid);
            if (tid == 0) cnt_wait(&g_cnt0[t], 64);
            __syncthreads();   // staging visible + cnt0 acquire propagated
            float d[2][8][4];
#pragma unroll
            for (int mt = 0; mt < 2; ++mt)
#pragma unroll
                for (int j = 0; j < 8; ++j)
#pragma unroll
                    for (int k = 0; k < 4; ++k) d[mt][j][k] = 0.0f;
            mma_x_global(d, Hf0 + (size_t)t * 32768, wf, wid, g, t4);
            mma_half_reg(d, hbf, wid, g, t4, wh, wl);
            store_pb(pb, d, wid, g, t4);
            __syncthreads();
            update_publish(pb, xbias, c, t, Hf1, Hbt, c1f, h1f, u0, ub, uug);
            __syncthreads();
            if (tid == 0) cnt_arrive(&g_cnt1[t]);
        }
    }
}

// ---------------- projection + mask ----------------
__global__ __launch_bounds__(256) void proj_kernel(
    const float* __restrict__ H, const float* __restrict__ Wo,
    const float* __restrict__ bo, const int* __restrict__ lens,
    float* __restrict__ out)
{
    __shared__ float hs[4][512];
    const int tid = threadIdx.x;
    const int row0 = blockIdx.x * 4;
    for (int idx = tid; idx < 4 * UU; idx += 256)
        hs[idx >> 9][idx & 511] = H[(size_t)row0 * UU + idx];
    __syncthreads();
    const int r = tid >> 6;
    const int cc = tid & 63;
    float acc = bo[cc];
#pragma unroll 8
    for (int k = 0; k < UU; ++k)
        acc = fmaf(hs[r][k], Wo[k * FF + cc], acc);
    const int row = row0 + r;
    const int b = row >> 8;
    const int t = row & 255;
    out[(size_t)row * FF + cc] = (t < lens[b]) ? acc : 0.0f;
}

// ---------------- launch ----------------
extern "C" void kernel_launch(void* const* d_in, const int* in_sizes, int n_in,
                              void* d_out, int out_size)
{
    const float* inputs  = (const float*)d_in[0];
    const float* targets = (const float*)d_in[1];
    const int*   tlen    = (const int*)d_in[2];
    const float* eW0 = (const float*)d_in[3];
    const float* eb0 = (const float*)d_in[4];
    const float* eW1 = (const float*)d_in[5];
    const float* eb1 = (const float*)d_in[6];
    const float* dW0 = (const float*)d_in[7];
    const float* db0 = (const float*)d_in[8];
    const float* dW1 = (const float*)d_in[9];
    const float* db1 = (const float*)d_in[10];
    const float* oW  = (const float*)d_in[11];
    const float* ob  = (const float*)d_in[12];
    float* out = (float*)d_out;

    float *Xg, *AT, *H1, *Hf0, *Hf1, *WFx, *zer, *cF, *hF, *cD, *hD;
    cudaGetSymbolAddress((void**)&Xg,  g_Xg);
    cudaGetSymbolAddress((void**)&AT,  g_AT);
    cudaGetSymbolAddress((void**)&H1,  g_H1);
    cudaGetSymbolAddress((void**)&Hf0, g_Hf0);
    cudaGetSymbolAddress((void**)&Hf1, g_Hf1);
    cudaGetSymbolAddress((void**)&WFx, g_WFx);
    cudaGetSymbolAddress((void**)&zer, g_zeros);
    cudaGetSymbolAddress((void**)&cF,  g_cF);
    cudaGetSymbolAddress((void**)&hF,  g_hF);
    cudaGetSymbolAddress((void**)&cD,  g_cD);
    cudaGetSymbolAddress((void**)&hD,  g_hD);

    cudaFuncSetAttribute(lstm_fused_kernel,
                         cudaFuncAttributeMaxDynamicSharedMemorySize, REC_SMEM);

    dim3 gx(G4U / 64, TT);   // (32, 256)

    // ---- encoder ----
    reset_cnt_kernel<<<1, 256>>>();
    transpose_in_kernel<<<TT, 256>>>(inputs, AT);
    xgemm64_kernel<<<gx, 256>>>(AT, eW0, eb0, Xg);
    prep_wfx_kernel<<<64, 256>>>(eW1, WFx);
    lstm_fused_kernel<<<128, 256, REC_SMEM>>>(
        Xg, eW0 + (size_t)FF * G4U, eW1, eb1, WFx,
        zer, zer, zer, zer,
        Hf0, Hf1, (float*)0,
        cF, hF, cF + BB * UU, hF + BB * UU);
    // ---- decoder ----
    reset_cnt_kernel<<<1, 256>>>();
    transpose_in_kernel<<<TT, 256>>>(targets, AT);
    xgemm64_kernel<<<gx, 256>>>(AT, dW0, db0, Xg);
    prep_wfx_kernel<<<64, 256>>>(dW1, WFx);
    lstm_fused_kernel<<<128, 256, REC_SMEM>>>(
        Xg, dW0 + (size_t)FF * G4U, dW1, db1, WFx,
        cF, hF, cF + BB * UU, hF + BB * UU,
        Hf0, Hf1, H1,
        cD, hD, cD + BB * UU, hD + BB * UU);
    // ---- projection ----
    proj_kernel<<<NROW / 4, 256>>>(H1, oW, ob, tlen, out);
}